// round 4
// baseline (speedup 1.0000x reference)
#include <cuda_runtime.h>
#include <cuda_bf16.h>
#include <math.h>
#include <stdint.h>

// ---------------- problem constants ----------------
#define BB 2
#define SS 2048
#define DD 512
#define HH 8
#define NROWS (BB*SS)            // 4096
#define MWORDS (SS/32)           // 64
#define NRAND (SS*SS/2)          // 2097152 (power of two)
#define NEG_HUGE (-3.4028234663852886e38f)
#define TINYF 1.17549435e-38f

// PRNG variant: partitionable threefry (modern JAX default).
#define TF_PARTITIONABLE 1

// ---------------- scratch (device globals; no runtime alloc) ----------------
__device__ float g_QN[NROWS*DD];
__device__ float g_KN[NROWS*DD];
__device__ float g_VN[NROWS*DD];
__device__ float g_Qh[NROWS*DD];
__device__ float g_Kh[NROWS*DD];
__device__ float g_Vh[NROWS*DD];
__device__ float g_CTX[NROWS*DD];
__device__ float g_HID[NROWS*128];
__device__ unsigned g_MASK[NROWS*MWORDS];
__device__ float g_DM[NROWS], g_CH[NROWS], g_MAG[NROWS], g_VAR1[NROWS], g_IMP[NROWS];
__device__ int   g_WIN[NROWS];
__device__ unsigned char g_KPB[NROWS];
__device__ unsigned g_KPW[BB*MWORDS];
__device__ unsigned g_CSW[BB*MWORDS];
__device__ float g_THR[BB], g_COMP[BB], g_IMPLO[BB], g_IMPHI[BB];
__device__ int   g_HASKP[BB], g_COUNT[BB], g_NEEDED[BB];
__device__ unsigned g_KEY_G[2], g_KEY_Q[2], g_KEY_K[2];

// ---------------- threefry-2x32 (JAX 20-round) ----------------
__device__ __forceinline__ void tf2x32(unsigned k0, unsigned k1, unsigned x0, unsigned x1,
                                       unsigned &o0, unsigned &o1) {
    unsigned ks2 = k0 ^ k1 ^ 0x1BD11BDAu;
    x0 += k0; x1 += k1;
#define TFR(r) { x0 += x1; x1 = (x1 << r) | (x1 >> (32 - r)); x1 ^= x0; }
    TFR(13) TFR(15) TFR(26) TFR(6)
    x0 += k1;  x1 += ks2 + 1u;
    TFR(17) TFR(29) TFR(16) TFR(24)
    x0 += ks2; x1 += k0 + 2u;
    TFR(13) TFR(15) TFR(26) TFR(6)
    x0 += k0;  x1 += k1 + 3u;
    TFR(17) TFR(29) TFR(16) TFR(24)
    x0 += k1;  x1 += ks2 + 4u;
    TFR(13) TFR(15) TFR(26) TFR(6)
    x0 += ks2; x1 += k0 + 5u;
#undef TFR
    o0 = x0; o1 = x1;
}

__device__ __forceinline__ unsigned tf_bits(unsigned k0, unsigned k1,
                                            unsigned long long idx,
                                            unsigned long long total) {
#if TF_PARTITIONABLE
    unsigned o0, o1;
    tf2x32(k0, k1, (unsigned)(idx >> 32), (unsigned)idx, o0, o1);
    return o0 ^ o1;
#else
    unsigned long long half = (total + 1ull) / 2ull;
    unsigned o0, o1;
    if (idx < half) { tf2x32(k0, k1, (unsigned)idx, (unsigned)(idx + half), o0, o1); return o0; }
    else            { tf2x32(k0, k1, (unsigned)(idx - half), (unsigned)idx, o0, o1); return o1; }
#endif
}

// ---------------- block reductions (caller provides smem of blockDim size) ----
__device__ __forceinline__ float bredSum(float v, float* s, int n) {
    int t = threadIdx.x; s[t] = v; __syncthreads();
    for (int k = n >> 1; k > 0; k >>= 1) { if (t < k) s[t] += s[t + k]; __syncthreads(); }
    float r = s[0]; __syncthreads(); return r;
}
__device__ __forceinline__ float bredMax(float v, float* s, int n) {
    int t = threadIdx.x; s[t] = v; __syncthreads();
    for (int k = n >> 1; k > 0; k >>= 1) { if (t < k) s[t] = fmaxf(s[t], s[t + k]); __syncthreads(); }
    float r = s[0]; __syncthreads(); return r;
}
__device__ __forceinline__ float bredMin(float v, float* s, int n) {
    int t = threadIdx.x; s[t] = v; __syncthreads();
    for (int k = n >> 1; k > 0; k >>= 1) { if (t < k) s[t] = fminf(s[t], s[t + k]); __syncthreads(); }
    float r = s[0]; __syncthreads(); return r;
}

// ---------------- init: clear per-call state, derive PRNG keys ----------------
__global__ void init_kernel() {
    int t = blockIdx.x * blockDim.x + threadIdx.x;
    if (t < BB*MWORDS) g_CSW[t] = 0u;
    if (t < BB) g_COUNT[t] = 0;
    if (t == 0) {
        unsigned o0, o1, a0, a1;
        // gumbel key = fold_in(key(42), 0)
        tf2x32(0u, 42u, 0u, 0u, o0, o1); g_KEY_G[0] = o0; g_KEY_G[1] = o1;
#if TF_PARTITIONABLE
        // qr key = split(fold_in(key,1))[1] = tf(fold1, (0,1))
        tf2x32(0u, 42u, 0u, 1u, o0, o1);
        tf2x32(o0, o1, 0u, 1u, a0, a1); g_KEY_Q[0] = a0; g_KEY_Q[1] = a1;
        tf2x32(0u, 42u, 0u, 2u, o0, o1);
        tf2x32(o0, o1, 0u, 1u, a0, a1); g_KEY_K[0] = a0; g_KEY_K[1] = a1;
#else
        // original split: counts iota(4) -> pairs (0,2),(1,3); key1=(o1(0,2),o1(1,3))
        unsigned p0, p1, q0, q1;
        tf2x32(0u, 42u, 0u, 1u, o0, o1);
        tf2x32(o0, o1, 0u, 2u, p0, p1);
        tf2x32(o0, o1, 1u, 3u, q0, q1);
        g_KEY_Q[0] = p1; g_KEY_Q[1] = q1;
        tf2x32(0u, 42u, 0u, 2u, o0, o1);
        tf2x32(o0, o1, 0u, 2u, p0, p1);
        tf2x32(o0, o1, 1u, 3u, q0, q1);
        g_KEY_K[0] = p1; g_KEY_K[1] = q1;
#endif
    }
}

// ---------------- LayerNorm (+qn stats) ----------------
__global__ void ln_kernel(const float* __restrict__ x, const float* __restrict__ g,
                          const float* __restrict__ bta, float* __restrict__ y, int stats) {
    __shared__ float sb[256];
    int row = blockIdx.x, tid = threadIdx.x;
    const float* xr = x + (size_t)row * DD;
    float x0 = xr[tid], x1 = xr[tid + 256];
    float mu = bredSum(x0 + x1, sb, 256) * (1.f / 512.f);
    float d0 = x0 - mu, d1 = x1 - mu;
    float var = bredSum(d0 * d0 + d1 * d1, sb, 256) * (1.f / 512.f);
    float r = rsqrtf(var + 1e-5f);
    float y0 = d0 * r * g[tid] + bta[tid];
    float y1 = d1 * r * g[tid + 256] + bta[tid + 256];
    float* yr = y + (size_t)row * DD;
    yr[tid] = y0; yr[tid + 256] = y1;
    if (stats) {
        float sq = bredSum(y0 * y0 + y1 * y1, sb, 256);
        float sy = bredSum(y0 + y1, sb, 256);
        float my = sy * (1.f / 512.f);
        float e0 = y0 - my, e1 = y1 - my;
        float sd = bredSum(e0 * e0 + e1 * e1, sb, 256);
        if (tid == 0) { g_MAG[row] = sqrtf(sq); g_VAR1[row] = sd * (1.f / 511.f); }
    }
}

// ---------------- generic GEMM: C[4096][N] = A[4096][512] @ W[N][512]^T + b ----
__global__ void gemm_kernel(const float* __restrict__ A, const float* __restrict__ W,
                            const float* __restrict__ bias, const float* __restrict__ resid,
                            float* __restrict__ C, int N, int doRelu) {
    __shared__ float As[64][17];
    __shared__ float Ws[64][17];
    int row0 = blockIdx.y * 64;
    int col0 = blockIdx.x * 64;
    int tid = threadIdx.x;
    int tx = tid & 15, ty = tid >> 4;
    int r0 = ty * 4, c0 = tx * 4;
    int lr = tid >> 2, lc4 = (tid & 3) * 4;
    float acc[4][4] = {};
    for (int kk = 0; kk < 512; kk += 16) {
        float4 av = *reinterpret_cast<const float4*>(A + (size_t)(row0 + lr) * 512 + kk + lc4);
        float4 wv = *reinterpret_cast<const float4*>(W + (size_t)(col0 + lr) * 512 + kk + lc4);
        As[lr][lc4] = av.x; As[lr][lc4+1] = av.y; As[lr][lc4+2] = av.z; As[lr][lc4+3] = av.w;
        Ws[lr][lc4] = wv.x; Ws[lr][lc4+1] = wv.y; Ws[lr][lc4+2] = wv.z; Ws[lr][lc4+3] = wv.w;
        __syncthreads();
#pragma unroll
        for (int kc = 0; kc < 16; kc++) {
            float a0 = As[r0][kc], a1 = As[r0+1][kc], a2 = As[r0+2][kc], a3 = As[r0+3][kc];
            float b0 = Ws[c0][kc], b1 = Ws[c0+1][kc], b2 = Ws[c0+2][kc], b3 = Ws[c0+3][kc];
            acc[0][0] += a0*b0; acc[0][1] += a0*b1; acc[0][2] += a0*b2; acc[0][3] += a0*b3;
            acc[1][0] += a1*b0; acc[1][1] += a1*b1; acc[1][2] += a1*b2; acc[1][3] += a1*b3;
            acc[2][0] += a2*b0; acc[2][1] += a2*b1; acc[2][2] += a2*b2; acc[2][3] += a2*b3;
            acc[3][0] += a3*b0; acc[3][1] += a3*b1; acc[3][2] += a3*b2; acc[3][3] += a3*b3;
        }
        __syncthreads();
    }
#pragma unroll
    for (int i = 0; i < 4; i++) {
#pragma unroll
        for (int j = 0; j < 4; j++) {
            int col = col0 + c0 + j;
            size_t ro = (size_t)(row0 + r0 + i);
            float v = acc[i][j] + bias[col];
            if (doRelu) v = fmaxf(v, 0.f);
            if (resid) v += resid[ro * (size_t)N + col];
            C[ro * (size_t)N + col] = v;
        }
    }
}

// ---------------- window reduce: win = clip(rint(64*(0.5+sigmoid(h.W2+b2))),1,128) --
__global__ void winred_kernel(const float* __restrict__ W2, const float* __restrict__ b2) {
    __shared__ float sb[128];
    int row = blockIdx.x, tid = threadIdx.x;
    sb[tid] = g_HID[(size_t)row * 128 + tid] * W2[tid];
    __syncthreads();
    for (int st = 64; st > 0; st >>= 1) { if (tid < st) sb[tid] += sb[tid + st]; __syncthreads(); }
    if (tid == 0) {
        float s = sb[0] + b2[0];
        float adj = 0.5f + 1.0f / (1.0f + expf(-s));
        int w = (int)rintf(64.0f * adj);
        g_WIN[row] = min(max(w, 1), 128);
    }
}

// ---------------- dm (multi-scale), ch, imp ----------------
__global__ void dm_kernel() {
    __shared__ float sb[256];
    int row = blockIdx.x, tid = threadIdx.x;
    int t = row & (SS - 1);
    const float* q0 = g_QN + (size_t)row * DD;
    float acc = 0.f, chs = 0.f;
    const int   sv[4] = {1, 2, 3, 5};
    const float wv[4] = {0.4f, 0.3f, 0.2f, 0.1f};
    for (int l = 0; l < 2; l++) {
        int d = tid + l * 256;
        float base = q0[d];
#pragma unroll
        for (int si = 0; si < 4; si++) {
            int s = sv[si];
            if (t + s < SS)
                acc += wv[si] * (fabsf(q0[(size_t)s * DD + d] - base) / (float)s);
        }
        if (t < SS - 1) chs += fabsf(q0[DD + d] - base);
    }
    float a = bredSum(acc, sb, 256);
    float c = bredSum(chs, sb, 256);
    if (tid == 0) {
        float chv = c * (1.f / 512.f);
        g_DM[row] = a * (1.f / 512.f);
        g_CH[row] = chv;
        g_IMP[row] = 0.5f * g_MAG[row] + 0.5f * chv;
    }
}

// ---------------- per-batch stats: thr, comp, imp lo/hi ----------------
__global__ void batchstat_kernel() {
    __shared__ float sb[1024];
    int b = blockIdx.x, tid = threadIdx.x;
    int r0 = b * SS + tid, r1 = r0 + 1024;
    float d0 = g_DM[r0], d1 = g_DM[r1];
    float mean = bredSum(d0 + d1, sb, 1024) * (1.f / 2048.f);
    float e0 = d0 - mean, e1 = d1 - mean;
    float var = bredSum(e0 * e0 + e1 * e1, sb, 1024) * (1.f / 2047.f);
    float comp = bredSum(g_VAR1[r0] + g_VAR1[r1], sb, 1024) * (1.f / 2048.f);
    float i0 = g_IMP[r0], i1 = g_IMP[r1];
    float lo = bredMin(fminf(i0, i1), sb, 1024);
    float hi = bredMax(fmaxf(i0, i1), sb, 1024);
    if (tid == 0) {
        g_THR[b] = mean + 0.5f * sqrtf(var);
        g_COMP[b] = comp;
        g_IMPLO[b] = lo; g_IMPHI[b] = hi;
    }
}

// ---------------- keypoints ----------------
__global__ void kp_kernel() {
    __shared__ unsigned char kpf[SS];
    __shared__ int anyf;
    int b = blockIdx.x, tid = threadIdx.x;
    if (tid == 0) anyf = 0;
    __syncthreads();
    float thr = g_THR[b];
    for (int it = 0; it < 2; it++) {
        int t = tid + it * 1024;
        int row = b * SS + t;
        float dm = g_DM[row];
        float left  = (t > 0)      ? g_DM[row - 1] : -1.0f;
        float right = (t < SS - 1) ? g_DM[row + 1] : -1.0f;
        int kp = (dm > thr) && (dm > left) && (dm > right);
        if (t == 0 || t == SS - 1) kp = kp || (dm > thr);
        kpf[t] = (unsigned char)kp;
        g_KPB[row] = (unsigned char)kp;
        if (kp) anyf = 1;
    }
    __syncthreads();
    if (tid < MWORDS) {
        unsigned w = 0;
        for (int j = 0; j < 32; j++) if (kpf[tid * 32 + j]) w |= (1u << j);
        g_KPW[b * MWORDS + tid] = w;
    }
    if (tid == 0) g_HASKP[b] = anyf;
}

// ---------------- stratified gumbel top-4 per segment ----------------
__global__ void gumbel_kernel() {
    __shared__ float sb[512];
    __shared__ float lv[512];
    __shared__ int si[512];
    int seg = blockIdx.x;           // 0..7 = b*4 + l
    int b = seg >> 2, l = seg & 3;
    int tid = threadIdx.x;
    int t = l * 512 + tid;
    int row = b * SS + t;
    float lo = g_IMPLO[b], hi = g_IMPHI[b];
    float ip = (g_IMP[row] - lo) / (hi - lo + 1e-6f);
    float ssum = bredSum(ip, sb, 512);
    float prob = ip / (ssum + 1e-6f);
    unsigned bits = tf_bits(g_KEY_G[0], g_KEY_G[1], (unsigned long long)(seg * 512 + tid), 4096ull);
    float f = __uint_as_float((bits >> 9) | 0x3f800000u) - 1.0f;
    float u = fmaxf(TINYF, f * (1.0f - TINYF) + TINYF);
    float gum = -logf(-logf(u));
    lv[tid] = logf(prob + 1e-20f) + gum;
    __syncthreads();
    for (int round = 0; round < 4; round++) {
        sb[tid] = lv[tid]; si[tid] = tid;
        __syncthreads();
        for (int st = 256; st > 0; st >>= 1) {
            if (tid < st) {
                float ov = sb[tid + st]; int oi = si[tid + st];
                if (ov > sb[tid] || (ov == sb[tid] && oi < si[tid])) { sb[tid] = ov; si[tid] = oi; }
            }
            __syncthreads();
        }
        if (tid == 0) {
            int sel = si[0];
            int tt = l * 512 + sel;
            atomicOr(&g_CSW[b * MWORDS + (tt >> 5)], 1u << (tt & 31));
            lv[sel] = -INFINITY;
        }
        __syncthreads();
    }
}

// ---------------- mask build + density ----------------
__device__ __forceinline__ unsigned range_word(int lo, int hi, int kb) {
    int a = lo - kb, e = hi - kb;
    if (e < 0 || a > 31) return 0u;
    a = max(a, 0); e = min(e, 31);
    unsigned m = (e == 31) ? 0xFFFFFFFFu : ((1u << (e + 1)) - 1u);
    return m & (0xFFFFFFFFu << a);
}

__global__ void maskbuild_kernel() {
    int row = blockIdx.x;
    int b = row >> 11, q = row & (SS - 1);
    int w = threadIdx.x;
    int kb = w * 32;
    int win = g_WIN[row];
    unsigned m = range_word(max(q - win, 0), min(q + win, SS - 1), kb);
    if (g_HASKP[b]) {
        m |= g_KPB[row] ? 0xFFFFFFFFu : g_KPW[b * MWORDS + w];
    } else {
        unsigned fbw = ((w == 0) ? 1u : 0u) | (((w & 15) == 15) ? 0x80000000u : 0u);
        int qin = (q == 0 || q == 511 || q == 1023 || q == 1535 || q == 2047);
        m |= qin ? 0xFFFFFFFFu : fbw;
    }
    m |= g_CSW[b * MWORDS + w];
    g_MASK[(size_t)row * MWORDS + w] = m;
    int pc = __popc(m);
#pragma unroll
    for (int o = 16; o > 0; o >>= 1) pc += __shfl_down_sync(0xffffffffu, pc, o);
    __shared__ int ws[2];
    if ((w & 31) == 0) ws[w >> 5] = pc;
    __syncthreads();
    if (w == 0) atomicAdd(&g_COUNT[b], ws[0] + ws[1]);
}

// ---------------- needed (ratio/density) ----------------
__global__ void needed_kernel() {
    if (threadIdx.x == 0) {
        float c0 = g_COMP[0], c1 = g_COMP[1];
        float mn = fminf(c0, c1), mx = fmaxf(c0, c1);
        for (int b = 0; b < BB; b++) {
            float nc = (g_COMP[b] - mn) / (mx - mn + 1e-6f);
            float ratio = fminf(fmaxf(0.3f * (0.5f + nc), 0.1f), 0.5f);
            float dens = (float)g_COUNT[b] / 4194304.0f;
            float nd = ceilf((ratio - dens) * 4194304.0f);
            int n = (int)nd;
            g_NEEDED[b] = max(n, 0);
        }
    }
}

// ---------------- random fill ----------------
__global__ void fill_kernel() {
    unsigned long long j = (unsigned long long)blockIdx.x * blockDim.x + threadIdx.x;
    if (j >= (unsigned long long)BB * NRAND) return;
    int b = (int)(j >> 21);
    int i = (int)(j & (NRAND - 1));
    if (i < g_NEEDED[b]) {
        unsigned qb = tf_bits(g_KEY_Q[0], g_KEY_Q[1], j, (unsigned long long)BB * NRAND);
        unsigned kb = tf_bits(g_KEY_K[0], g_KEY_K[1], j, (unsigned long long)BB * NRAND);
        int qr = qb & (SS - 1), kr = kb & (SS - 1);
        atomicOr(&g_MASK[((size_t)(b * SS + qr)) * MWORDS + (kr >> 5)], 1u << (kr & 31));
    }
}

// ---------------- attention (flash-style, 64x64 tiles, fp32) ----------------
#define ATT_SMEM_FLOATS (4*64*65 + 64*16 + 3*64)
__global__ void attn_kernel() {
    extern __shared__ float sm[];
    float* Qs = sm;
    float* Ks = Qs + 64 * 65;
    float* Vs = Ks + 64 * 65;
    float* Ps = Vs + 64 * 65;
    float* red = Ps + 64 * 65;
    float* rowm = red + 64 * 16;
    float* rowl = rowm + 64;
    float* rowsc = rowl + 64;

    int qt = blockIdx.x, bh = blockIdx.y;
    int b = bh >> 3, h = bh & 7;
    int q0 = qt * 64;
    int tid = threadIdx.x;
    int tx = tid & 15, ty = tid >> 4;
    int r0 = ty * 4, c0 = tx * 4;
    const size_t headoff = (size_t)h * 64;

    // load Q tile
    for (int it = 0; it < 4; it++) {
        int e = tid + it * 256;
        int lr = e >> 4, lc = (e & 15) * 4;
        float4 v = *reinterpret_cast<const float4*>(
            g_Qh + ((size_t)(b * SS + q0 + lr)) * DD + headoff + lc);
        Qs[lr * 65 + lc] = v.x; Qs[lr * 65 + lc + 1] = v.y;
        Qs[lr * 65 + lc + 2] = v.z; Qs[lr * 65 + lc + 3] = v.w;
    }
    if (tid < 64) { rowm[tid] = -INFINITY; rowl[tid] = 0.f; }
    float acc[4][4] = {};
    __syncthreads();

    for (int k0 = 0; k0 < SS; k0 += 64) {
        // load K,V tiles
        for (int it = 0; it < 4; it++) {
            int e = tid + it * 256;
            int lr = e >> 4, lc = (e & 15) * 4;
            size_t go = ((size_t)(b * SS + k0 + lr)) * DD + headoff + lc;
            float4 kv = *reinterpret_cast<const float4*>(g_Kh + go);
            float4 vv = *reinterpret_cast<const float4*>(g_Vh + go);
            Ks[lr * 65 + lc] = kv.x; Ks[lr * 65 + lc + 1] = kv.y;
            Ks[lr * 65 + lc + 2] = kv.z; Ks[lr * 65 + lc + 3] = kv.w;
            Vs[lr * 65 + lc] = vv.x; Vs[lr * 65 + lc + 1] = vv.y;
            Vs[lr * 65 + lc + 2] = vv.z; Vs[lr * 65 + lc + 3] = vv.w;
        }
        __syncthreads();

        // GEMM1: S = Q K^T
        float s[4][4] = {};
#pragma unroll 8
        for (int d = 0; d < 64; d++) {
            float a0 = Qs[(r0) * 65 + d], a1 = Qs[(r0+1) * 65 + d];
            float a2 = Qs[(r0+2) * 65 + d], a3 = Qs[(r0+3) * 65 + d];
            float b0 = Ks[(c0) * 65 + d], b1 = Ks[(c0+1) * 65 + d];
            float b2 = Ks[(c0+2) * 65 + d], b3 = Ks[(c0+3) * 65 + d];
            s[0][0] += a0*b0; s[0][1] += a0*b1; s[0][2] += a0*b2; s[0][3] += a0*b3;
            s[1][0] += a1*b0; s[1][1] += a1*b1; s[1][2] += a1*b2; s[1][3] += a1*b3;
            s[2][0] += a2*b0; s[2][1] += a2*b1; s[2][2] += a2*b2; s[2][3] += a2*b3;
            s[3][0] += a3*b0; s[3][1] += a3*b1; s[3][2] += a3*b2; s[3][3] += a3*b3;
        }
        // scale + sparse mask (bit set => masked OUT)
#pragma unroll
        for (int i = 0; i < 4; i++) {
            unsigned mw = g_MASK[((size_t)(b * SS + q0 + r0 + i)) * MWORDS + ((k0 + c0) >> 5)];
#pragma unroll
            for (int j = 0; j < 4; j++) {
                int bit = (mw >> ((c0 + j) & 31)) & 1;
                s[i][j] = bit ? NEG_HUGE : s[i][j] * 0.125f;
            }
        }
        // row max partial
#pragma unroll
        for (int i = 0; i < 4; i++) {
            float tm = fmaxf(fmaxf(s[i][0], s[i][1]), fmaxf(s[i][2], s[i][3]));
            red[(r0 + i) * 16 + tx] = tm;
        }
        __syncthreads();
        if (tid < 64) {
            float rm = red[tid * 16];
#pragma unroll
            for (int t2 = 1; t2 < 16; t2++) rm = fmaxf(rm, red[tid * 16 + t2]);
            float mo = rowm[tid], mn = fmaxf(mo, rm);
            rowsc[tid] = expf(mo - mn);
            rowm[tid] = mn;
        }
        __syncthreads();
        // exp, write P, partial sums, rescale acc
#pragma unroll
        for (int i = 0; i < 4; i++) {
            float mi = rowm[r0 + i], sc = rowsc[r0 + i];
            float ts = 0.f;
#pragma unroll
            for (int j = 0; j < 4; j++) {
                float p = expf(s[i][j] - mi);
                Ps[(r0 + i) * 65 + c0 + j] = p;
                ts += p;
                acc[i][j] *= sc;
            }
            red[(r0 + i) * 16 + tx] = ts;
        }
        __syncthreads();
        if (tid < 64) {
            float rs = 0.f;
#pragma unroll
            for (int t2 = 0; t2 < 16; t2++) rs += red[tid * 16 + t2];
            rowl[tid] = rowl[tid] * rowsc[tid] + rs;
        }
        // GEMM2: acc += P V   (Ps complete after the sync above)
#pragma unroll 8
        for (int c = 0; c < 64; c++) {
            float a0 = Ps[(r0) * 65 + c], a1 = Ps[(r0+1) * 65 + c];
            float a2 = Ps[(r0+2) * 65 + c], a3 = Ps[(r0+3) * 65 + c];
            float b0 = Vs[c * 65 + c0], b1 = Vs[c * 65 + c0 + 1];
            float b2 = Vs[c * 65 + c0 + 2], b3 = Vs[c * 65 + c0 + 3];
            acc[0][0] += a0*b0; acc[0][1] += a0*b1; acc[0][2] += a0*b2; acc[0][3] += a0*b3;
            acc[1][0] += a1*b0; acc[1][1] += a1*b1; acc[1][2] += a1*b2; acc[1][3] += a1*b3;
            acc[2][0] += a2*b0; acc[2][1] += a2*b1; acc[2][2] += a2*b2; acc[2][3] += a2*b3;
            acc[3][0] += a3*b0; acc[3][1] += a3*b1; acc[3][2] += a3*b2; acc[3][3] += a3*b3;
        }
        __syncthreads();
    }
    // epilogue
#pragma unroll
    for (int i = 0; i < 4; i++) {
        float inv = 1.0f / rowl[r0 + i];
#pragma unroll
        for (int j = 0; j < 4; j++) {
            g_CTX[((size_t)(b * SS + q0 + r0 + i)) * DD + headoff + c0 + j] = acc[i][j] * inv;
        }
    }
}

// ---------------- launch ----------------
extern "C" void kernel_launch(void* const* d_in, const int* in_sizes, int n_in,
                              void* d_out, int out_size) {
    const float* queries = (const float*)d_in[0];
    const float* keys    = (const float*)d_in[1];
    const float* values  = (const float*)d_in[2];
    const float* ln_q_g  = (const float*)d_in[3];
    const float* ln_q_b  = (const float*)d_in[4];
    const float* ln_k_g  = (const float*)d_in[5];
    const float* ln_k_b  = (const float*)d_in[6];
    const float* ln_v_g  = (const float*)d_in[7];
    const float* ln_v_b  = (const float*)d_in[8];
    const float* Wq = (const float*)d_in[9];   const float* bq = (const float*)d_in[10];
    const float* Wk = (const float*)d_in[11];  const float* bk = (const float*)d_in[12];
    const float* Wv = (const float*)d_in[13];  const float* bv = (const float*)d_in[14];
    const float* Wo = (const float*)d_in[15];  const float* bo = (const float*)d_in[16];
    const float* Ww1 = (const float*)d_in[17]; const float* bw1 = (const float*)d_in[18];
    const float* Ww2 = (const float*)d_in[19]; const float* bw2 = (const float*)d_in[20];
    float* out = (float*)d_out;

    float *QN, *KN, *VN, *Qh, *Kh, *Vh, *CTX, *HID;
    cudaGetSymbolAddress((void**)&QN, g_QN);
    cudaGetSymbolAddress((void**)&KN, g_KN);
    cudaGetSymbolAddress((void**)&VN, g_VN);
    cudaGetSymbolAddress((void**)&Qh, g_Qh);
    cudaGetSymbolAddress((void**)&Kh, g_Kh);
    cudaGetSymbolAddress((void**)&Vh, g_Vh);
    cudaGetSymbolAddress((void**)&CTX, g_CTX);
    cudaGetSymbolAddress((void**)&HID, g_HID);

    init_kernel<<<1, 128>>>();
    ln_kernel<<<NROWS, 256>>>(queries, ln_q_g, ln_q_b, QN, 1);
    ln_kernel<<<NROWS, 256>>>(keys,    ln_k_g, ln_k_b, KN, 0);
    ln_kernel<<<NROWS, 256>>>(values,  ln_v_g, ln_v_b, VN, 0);

    // hidden for window MLP (relu)
    gemm_kernel<<<dim3(2, 64), 256>>>(QN, Ww1, bw1, nullptr, HID, 128, 1);
    winred_kernel<<<NROWS, 128>>>(Ww2, bw2);

    dm_kernel<<<NROWS, 256>>>();
    batchstat_kernel<<<BB, 1024>>>();
    kp_kernel<<<BB, 1024>>>();
    gumbel_kernel<<<BB * 4, 512>>>();
    maskbuild_kernel<<<NROWS, 64>>>();
    needed_kernel<<<1, 32>>>();
    fill_kernel<<<(BB * NRAND) / 256, 256>>>();

    // projections
    gemm_kernel<<<dim3(8, 64), 256>>>(QN, Wq, bq, nullptr, Qh, 512, 0);
    gemm_kernel<<<dim3(8, 64), 256>>>(KN, Wk, bk, nullptr, Kh, 512, 0);
    gemm_kernel<<<dim3(8, 64), 256>>>(VN, Wv, bv, nullptr, Vh, 512, 0);

    // attention
    size_t smem = ATT_SMEM_FLOATS * sizeof(float);
    cudaFuncSetAttribute(attn_kernel, cudaFuncAttributeMaxDynamicSharedMemorySize, (int)smem);
    attn_kernel<<<dim3(SS / 64, BB * HH), 256, smem>>>();

    // output projection + residual
    gemm_kernel<<<dim3(8, 64), 256>>>(CTX, Wo, bo, queries, out, 512, 0);
}

// round 6
// speedup vs baseline: 2.0859x; 2.0859x over previous
#include <cuda_runtime.h>
#include <cuda_bf16.h>
#include <math.h>
#include <stdint.h>

// ---------------- problem constants ----------------
#define BB 2
#define SS 2048
#define DD 512
#define HH 8
#define NROWS (BB*SS)            // 4096
#define MWORDS (SS/32)           // 64
#define NRAND (SS*SS/2)          // 2097152 (power of two)
#define NEG_HUGE (-3.4028234663852886e38f)
#define TINYF 1.17549435e-38f

#define TF_PARTITIONABLE 1

// ---------------- scratch (device globals; no runtime alloc) ----------------
__device__ float g_QN[NROWS*DD];
__device__ float g_KN[NROWS*DD];
__device__ float g_VN[NROWS*DD];
__device__ float g_Qh[NROWS*DD];
__device__ float g_Kh[NROWS*DD];
__device__ float g_Vh[NROWS*DD];
__device__ float g_CTX[NROWS*DD];
__device__ float g_HID[NROWS*128];
__device__ unsigned g_MASK[NROWS*MWORDS];
__device__ float g_DM[NROWS], g_CH[NROWS], g_MAG[NROWS], g_VAR1[NROWS], g_IMP[NROWS];
__device__ int   g_WIN[NROWS];
__device__ unsigned char g_KPB[NROWS];
__device__ unsigned g_KPW[BB*MWORDS];
__device__ unsigned g_CSW[BB*MWORDS];
__device__ float g_THR[BB], g_COMP[BB], g_IMPLO[BB], g_IMPHI[BB];
__device__ int   g_HASKP[BB], g_COUNT[BB], g_NEEDED[BB];
__device__ unsigned g_KEY_G[2], g_KEY_Q[2], g_KEY_K[2];

// ---------------- threefry-2x32 (JAX 20-round) ----------------
__device__ __forceinline__ void tf2x32(unsigned k0, unsigned k1, unsigned x0, unsigned x1,
                                       unsigned &o0, unsigned &o1) {
    unsigned ks2 = k0 ^ k1 ^ 0x1BD11BDAu;
    x0 += k0; x1 += k1;
#define TFR(r) { x0 += x1; x1 = (x1 << r) | (x1 >> (32 - r)); x1 ^= x0; }
    TFR(13) TFR(15) TFR(26) TFR(6)
    x0 += k1;  x1 += ks2 + 1u;
    TFR(17) TFR(29) TFR(16) TFR(24)
    x0 += ks2; x1 += k0 + 2u;
    TFR(13) TFR(15) TFR(26) TFR(6)
    x0 += k0;  x1 += k1 + 3u;
    TFR(17) TFR(29) TFR(16) TFR(24)
    x0 += k1;  x1 += ks2 + 4u;
    TFR(13) TFR(15) TFR(26) TFR(6)
    x0 += ks2; x1 += k0 + 5u;
#undef TFR
    o0 = x0; o1 = x1;
}

__device__ __forceinline__ unsigned tf_bits(unsigned k0, unsigned k1,
                                            unsigned long long idx,
                                            unsigned long long total) {
#if TF_PARTITIONABLE
    unsigned o0, o1;
    tf2x32(k0, k1, (unsigned)(idx >> 32), (unsigned)idx, o0, o1);
    return o0 ^ o1;
#else
    unsigned long long half = (total + 1ull) / 2ull;
    unsigned o0, o1;
    if (idx < half) { tf2x32(k0, k1, (unsigned)idx, (unsigned)(idx + half), o0, o1); return o0; }
    else            { tf2x32(k0, k1, (unsigned)(idx - half), (unsigned)idx, o0, o1); return o1; }
#endif
}

// ---------------- tf32 helpers ----------------
__device__ __forceinline__ unsigned f2tf32(float x) {
    unsigned r;
    asm("cvt.rna.tf32.f32 %0, %1;" : "=r"(r) : "f"(x));
    return r;
}

__device__ __forceinline__ void mma_tf32(float d[4], const unsigned a[4],
                                         unsigned b0, unsigned b1) {
    asm volatile("mma.sync.aligned.m16n8k8.row.col.f32.tf32.tf32.f32 "
        "{%0,%1,%2,%3}, {%4,%5,%6,%7}, {%8,%9}, {%0,%1,%2,%3};"
        : "+f"(d[0]), "+f"(d[1]), "+f"(d[2]), "+f"(d[3])
        : "r"(a[0]), "r"(a[1]), "r"(a[2]), "r"(a[3]), "r"(b0), "r"(b1));
}

// ---------------- block reductions ----------------
__device__ __forceinline__ float bredSum(float v, float* s, int n) {
    int t = threadIdx.x; s[t] = v; __syncthreads();
    for (int k = n >> 1; k > 0; k >>= 1) { if (t < k) s[t] += s[t + k]; __syncthreads(); }
    float r = s[0]; __syncthreads(); return r;
}
__device__ __forceinline__ float bredMax(float v, float* s, int n) {
    int t = threadIdx.x; s[t] = v; __syncthreads();
    for (int k = n >> 1; k > 0; k >>= 1) { if (t < k) s[t] = fmaxf(s[t], s[t + k]); __syncthreads(); }
    float r = s[0]; __syncthreads(); return r;
}
__device__ __forceinline__ float bredMin(float v, float* s, int n) {
    int t = threadIdx.x; s[t] = v; __syncthreads();
    for (int k = n >> 1; k > 0; k >>= 1) { if (t < k) s[t] = fminf(s[t], s[t + k]); __syncthreads(); }
    float r = s[0]; __syncthreads(); return r;
}

// ---------------- init ----------------
__global__ void init_kernel() {
    int t = blockIdx.x * blockDim.x + threadIdx.x;
    if (t < BB*MWORDS) g_CSW[t] = 0u;
    if (t < BB) g_COUNT[t] = 0;
    if (t == 0) {
        unsigned o0, o1, a0, a1;
        tf2x32(0u, 42u, 0u, 0u, o0, o1); g_KEY_G[0] = o0; g_KEY_G[1] = o1;
#if TF_PARTITIONABLE
        tf2x32(0u, 42u, 0u, 1u, o0, o1);
        tf2x32(o0, o1, 0u, 1u, a0, a1); g_KEY_Q[0] = a0; g_KEY_Q[1] = a1;
        tf2x32(0u, 42u, 0u, 2u, o0, o1);
        tf2x32(o0, o1, 0u, 1u, a0, a1); g_KEY_K[0] = a0; g_KEY_K[1] = a1;
#else
        unsigned p0, p1, q0, q1;
        tf2x32(0u, 42u, 0u, 1u, o0, o1);
        tf2x32(o0, o1, 0u, 2u, p0, p1);
        tf2x32(o0, o1, 1u, 3u, q0, q1);
        g_KEY_Q[0] = p1; g_KEY_Q[1] = q1;
        tf2x32(0u, 42u, 0u, 2u, o0, o1);
        tf2x32(o0, o1, 0u, 2u, p0, p1);
        tf2x32(o0, o1, 1u, 3u, q0, q1);
        g_KEY_K[0] = p1; g_KEY_K[1] = q1;
#endif
    }
}

// ---------------- warp-per-row LayerNorm (+qn stats) ----------------
__global__ void ln_warp_kernel(const float* __restrict__ x, const float* __restrict__ gam,
                               const float* __restrict__ bet, float* __restrict__ y, int stats) {
    int w = threadIdx.x >> 5, lane = threadIdx.x & 31;
    int row = blockIdx.x * 8 + w;
    const float4* xr = (const float4*)(x + (size_t)row * 512);
    float4 v[4];
#pragma unroll
    for (int j = 0; j < 4; j++) v[j] = xr[lane + j * 32];
    float s = 0.f;
#pragma unroll
    for (int j = 0; j < 4; j++) s += v[j].x + v[j].y + v[j].z + v[j].w;
#pragma unroll
    for (int o = 16; o > 0; o >>= 1) s += __shfl_xor_sync(0xffffffffu, s, o);
    float mu = s * (1.f / 512.f);
    float qv = 0.f;
#pragma unroll
    for (int j = 0; j < 4; j++) {
        float a = v[j].x - mu, b = v[j].y - mu, c = v[j].z - mu, d = v[j].w - mu;
        qv += a * a + b * b + c * c + d * d;
    }
#pragma unroll
    for (int o = 16; o > 0; o >>= 1) qv += __shfl_xor_sync(0xffffffffu, qv, o);
    float r = rsqrtf(qv * (1.f / 512.f) + 1e-5f);
    const float4* g4 = (const float4*)gam;
    const float4* b4 = (const float4*)bet;
    float4* yr = (float4*)(y + (size_t)row * 512);
    float yv[16];
#pragma unroll
    for (int j = 0; j < 4; j++) {
        float4 gg = g4[lane + j * 32], bb = b4[lane + j * 32];
        float4 o4;
        o4.x = (v[j].x - mu) * r * gg.x + bb.x;
        o4.y = (v[j].y - mu) * r * gg.y + bb.y;
        o4.z = (v[j].z - mu) * r * gg.z + bb.z;
        o4.w = (v[j].w - mu) * r * gg.w + bb.w;
        yr[lane + j * 32] = o4;
        yv[j*4+0] = o4.x; yv[j*4+1] = o4.y; yv[j*4+2] = o4.z; yv[j*4+3] = o4.w;
    }
    if (stats) {
        float sq = 0.f, sy = 0.f;
#pragma unroll
        for (int i = 0; i < 16; i++) { sq += yv[i] * yv[i]; sy += yv[i]; }
#pragma unroll
        for (int o = 16; o > 0; o >>= 1) {
            sq += __shfl_xor_sync(0xffffffffu, sq, o);
            sy += __shfl_xor_sync(0xffffffffu, sy, o);
        }
        float my = sy * (1.f / 512.f);
        float sd = 0.f;
#pragma unroll
        for (int i = 0; i < 16; i++) { float e = yv[i] - my; sd += e * e; }
#pragma unroll
        for (int o = 16; o > 0; o >>= 1) sd += __shfl_xor_sync(0xffffffffu, sd, o);
        if (lane == 0) { g_MAG[row] = sqrtf(sq); g_VAR1[row] = sd * (1.f / 511.f); }
    }
}

// ---------------- fp32 GEMM (kept for window-MLP hidden only) ----------------
__global__ void gemm_kernel(const float* __restrict__ A, const float* __restrict__ W,
                            const float* __restrict__ bias, const float* __restrict__ resid,
                            float* __restrict__ C, int N, int doRelu) {
    __shared__ float As[64][17];
    __shared__ float Ws[64][17];
    int row0 = blockIdx.y * 64;
    int col0 = blockIdx.x * 64;
    int tid = threadIdx.x;
    int tx = tid & 15, ty = tid >> 4;
    int r0 = ty * 4, c0 = tx * 4;
    int lr = tid >> 2, lc4 = (tid & 3) * 4;
    float acc[4][4] = {};
    for (int kk = 0; kk < 512; kk += 16) {
        float4 av = *reinterpret_cast<const float4*>(A + (size_t)(row0 + lr) * 512 + kk + lc4);
        float4 wv = *reinterpret_cast<const float4*>(W + (size_t)(col0 + lr) * 512 + kk + lc4);
        As[lr][lc4] = av.x; As[lr][lc4+1] = av.y; As[lr][lc4+2] = av.z; As[lr][lc4+3] = av.w;
        Ws[lr][lc4] = wv.x; Ws[lr][lc4+1] = wv.y; Ws[lr][lc4+2] = wv.z; Ws[lr][lc4+3] = wv.w;
        __syncthreads();
#pragma unroll
        for (int kc = 0; kc < 16; kc++) {
            float a0 = As[r0][kc], a1 = As[r0+1][kc], a2 = As[r0+2][kc], a3 = As[r0+3][kc];
            float b0 = Ws[c0][kc], b1 = Ws[c0+1][kc], b2 = Ws[c0+2][kc], b3 = Ws[c0+3][kc];
            acc[0][0] += a0*b0; acc[0][1] += a0*b1; acc[0][2] += a0*b2; acc[0][3] += a0*b3;
            acc[1][0] += a1*b0; acc[1][1] += a1*b1; acc[1][2] += a1*b2; acc[1][3] += a1*b3;
            acc[2][0] += a2*b0; acc[2][1] += a2*b1; acc[2][2] += a2*b2; acc[2][3] += a2*b3;
            acc[3][0] += a3*b0; acc[3][1] += a3*b1; acc[3][2] += a3*b2; acc[3][3] += a3*b3;
        }
        __syncthreads();
    }
#pragma unroll
    for (int i = 0; i < 4; i++) {
#pragma unroll
        for (int j = 0; j < 4; j++) {
            int col = col0 + c0 + j;
            size_t ro = (size_t)(row0 + r0 + i);
            float v = acc[i][j] + bias[col];
            if (doRelu) v = fmaxf(v, 0.f);
            if (resid) v += resid[ro * (size_t)N + col];
            C[ro * (size_t)N + col] = v;
        }
    }
}

// ---------------- tf32 MMA GEMM: C[4096][N] = A[4096][512] @ W[N][512]^T + b ----
__global__ void __launch_bounds__(128) gemm_mma_kernel(
        const float* __restrict__ A, const float* __restrict__ W,
        const float* __restrict__ bias, const float* __restrict__ resid,
        float* __restrict__ C, int N) {
    __shared__ unsigned As[64*36];
    __shared__ unsigned Ws[64*36];
    int tid = threadIdx.x;
    int w = tid >> 5, lane = tid & 31, g = lane >> 2, tig = lane & 3;
    int col0 = blockIdx.x * 64, row0 = blockIdx.y * 64;
    int wq = w * 16;
    float acc[8][4];
#pragma unroll
    for (int nt = 0; nt < 8; nt++) { acc[nt][0]=0; acc[nt][1]=0; acc[nt][2]=0; acc[nt][3]=0; }
    for (int kc = 0; kc < 512; kc += 32) {
#pragma unroll
        for (int it = 0; it < 4; it++) {
            int idx = tid + it * 128;
            int r = idx >> 3, c4 = (idx & 7) << 2;
            float4 av = *(const float4*)(A + (size_t)(row0 + r) * 512 + kc + c4);
            float4 wv = *(const float4*)(W + (size_t)(col0 + r) * 512 + kc + c4);
            As[r*36+c4+0] = f2tf32(av.x); As[r*36+c4+1] = f2tf32(av.y);
            As[r*36+c4+2] = f2tf32(av.z); As[r*36+c4+3] = f2tf32(av.w);
            Ws[r*36+c4+0] = f2tf32(wv.x); Ws[r*36+c4+1] = f2tf32(wv.y);
            Ws[r*36+c4+2] = f2tf32(wv.z); Ws[r*36+c4+3] = f2tf32(wv.w);
        }
        __syncthreads();
#pragma unroll
        for (int ks = 0; ks < 4; ks++) {
            unsigned a[4];
            a[0] = As[(wq+g)*36 + ks*8 + tig];
            a[1] = As[(wq+g+8)*36 + ks*8 + tig];
            a[2] = As[(wq+g)*36 + ks*8 + tig + 4];
            a[3] = As[(wq+g+8)*36 + ks*8 + tig + 4];
#pragma unroll
            for (int nt = 0; nt < 8; nt++) {
                unsigned b0 = Ws[(nt*8+g)*36 + ks*8 + tig];
                unsigned b1 = Ws[(nt*8+g)*36 + ks*8 + tig + 4];
                mma_tf32(acc[nt], a, b0, b1);
            }
        }
        __syncthreads();
    }
    int rlo = row0 + wq + g, rhi = rlo + 8;
#pragma unroll
    for (int nt = 0; nt < 8; nt++) {
        int c = col0 + nt*8 + 2*tig;
        float v0 = acc[nt][0] + bias[c],   v1 = acc[nt][1] + bias[c+1];
        float v2 = acc[nt][2] + bias[c],   v3 = acc[nt][3] + bias[c+1];
        if (resid) {
            v0 += resid[(size_t)rlo * N + c];   v1 += resid[(size_t)rlo * N + c + 1];
            v2 += resid[(size_t)rhi * N + c];   v3 += resid[(size_t)rhi * N + c + 1];
        }
        C[(size_t)rlo * N + c] = v0; C[(size_t)rlo * N + c + 1] = v1;
        C[(size_t)rhi * N + c] = v2; C[(size_t)rhi * N + c + 1] = v3;
    }
}

// ---------------- window reduce ----------------
__global__ void winred_kernel(const float* __restrict__ W2, const float* __restrict__ b2) {
    __shared__ float sb[128];
    int row = blockIdx.x, tid = threadIdx.x;
    sb[tid] = g_HID[(size_t)row * 128 + tid] * W2[tid];
    __syncthreads();
    for (int st = 64; st > 0; st >>= 1) { if (tid < st) sb[tid] += sb[tid + st]; __syncthreads(); }
    if (tid == 0) {
        float s = sb[0] + b2[0];
        float adj = 0.5f + 1.0f / (1.0f + expf(-s));
        int w = (int)rintf(64.0f * adj);
        g_WIN[row] = min(max(w, 1), 128);
    }
}

// ---------------- dm/ch/imp ----------------
__global__ void dm_kernel() {
    __shared__ float sb[256];
    int row = blockIdx.x, tid = threadIdx.x;
    int t = row & (SS - 1);
    const float* q0 = g_QN + (size_t)row * DD;
    float acc = 0.f, chs = 0.f;
    const int   sv[4] = {1, 2, 3, 5};
    const float wv[4] = {0.4f, 0.3f, 0.2f, 0.1f};
    for (int l = 0; l < 2; l++) {
        int d = tid + l * 256;
        float base = q0[d];
#pragma unroll
        for (int si = 0; si < 4; si++) {
            int s = sv[si];
            if (t + s < SS)
                acc += wv[si] * (fabsf(q0[(size_t)s * DD + d] - base) / (float)s);
        }
        if (t < SS - 1) chs += fabsf(q0[DD + d] - base);
    }
    float a = bredSum(acc, sb, 256);
    float c = bredSum(chs, sb, 256);
    if (tid == 0) {
        float chv = c * (1.f / 512.f);
        g_DM[row] = a * (1.f / 512.f);
        g_CH[row] = chv;
        g_IMP[row] = 0.5f * g_MAG[row] + 0.5f * chv;
    }
}

// ---------------- per-batch stats ----------------
__global__ void batchstat_kernel() {
    __shared__ float sb[1024];
    int b = blockIdx.x, tid = threadIdx.x;
    int r0 = b * SS + tid, r1 = r0 + 1024;
    float d0 = g_DM[r0], d1 = g_DM[r1];
    float mean = bredSum(d0 + d1, sb, 1024) * (1.f / 2048.f);
    float e0 = d0 - mean, e1 = d1 - mean;
    float var = bredSum(e0 * e0 + e1 * e1, sb, 1024) * (1.f / 2047.f);
    float comp = bredSum(g_VAR1[r0] + g_VAR1[r1], sb, 1024) * (1.f / 2048.f);
    float i0 = g_IMP[r0], i1 = g_IMP[r1];
    float lo = bredMin(fminf(i0, i1), sb, 1024);
    float hi = bredMax(fmaxf(i0, i1), sb, 1024);
    if (tid == 0) {
        g_THR[b] = mean + 0.5f * sqrtf(var);
        g_COMP[b] = comp;
        g_IMPLO[b] = lo; g_IMPHI[b] = hi;
    }
}

// ---------------- keypoints ----------------
__global__ void kp_kernel() {
    __shared__ unsigned char kpf[SS];
    __shared__ int anyf;
    int b = blockIdx.x, tid = threadIdx.x;
    if (tid == 0) anyf = 0;
    __syncthreads();
    float thr = g_THR[b];
    for (int it = 0; it < 2; it++) {
        int t = tid + it * 1024;
        int row = b * SS + t;
        float dm = g_DM[row];
        float left  = (t > 0)      ? g_DM[row - 1] : -1.0f;
        float right = (t < SS - 1) ? g_DM[row + 1] : -1.0f;
        int kp = (dm > thr) && (dm > left) && (dm > right);
        if (t == 0 || t == SS - 1) kp = kp || (dm > thr);
        kpf[t] = (unsigned char)kp;
        g_KPB[row] = (unsigned char)kp;
        if (kp) anyf = 1;
    }
    __syncthreads();
    if (tid < MWORDS) {
        unsigned w = 0;
        for (int j = 0; j < 32; j++) if (kpf[tid * 32 + j]) w |= (1u << j);
        g_KPW[b * MWORDS + tid] = w;
    }
    if (tid == 0) g_HASKP[b] = anyf;
}

// ---------------- stratified gumbel top-4 ----------------
__global__ void gumbel_kernel() {
    __shared__ float sb[512];
    __shared__ float lv[512];
    __shared__ int si[512];
    int seg = blockIdx.x;
    int b = seg >> 2, l = seg & 3;
    int tid = threadIdx.x;
    int t = l * 512 + tid;
    int row = b * SS + t;
    float lo = g_IMPLO[b], hi = g_IMPHI[b];
    float ip = (g_IMP[row] - lo) / (hi - lo + 1e-6f);
    float ssum = bredSum(ip, sb, 512);
    float prob = ip / (ssum + 1e-6f);
    unsigned bits = tf_bits(g_KEY_G[0], g_KEY_G[1], (unsigned long long)(seg * 512 + tid), 4096ull);
    float f = __uint_as_float((bits >> 9) | 0x3f800000u) - 1.0f;
    float u = fmaxf(TINYF, f * (1.0f - TINYF) + TINYF);
    float gum = -logf(-logf(u));
    lv[tid] = logf(prob + 1e-20f) + gum;
    __syncthreads();
    for (int round = 0; round < 4; round++) {
        sb[tid] = lv[tid]; si[tid] = tid;
        __syncthreads();
        for (int st = 256; st > 0; st >>= 1) {
            if (tid < st) {
                float ov = sb[tid + st]; int oi = si[tid + st];
                if (ov > sb[tid] || (ov == sb[tid] && oi < si[tid])) { sb[tid] = ov; si[tid] = oi; }
            }
            __syncthreads();
        }
        if (tid == 0) {
            int sel = si[0];
            int tt = l * 512 + sel;
            atomicOr(&g_CSW[b * MWORDS + (tt >> 5)], 1u << (tt & 31));
            lv[sel] = -INFINITY;
        }
        __syncthreads();
    }
}

// ---------------- mask build + density ----------------
__device__ __forceinline__ unsigned range_word(int lo, int hi, int kb) {
    int a = lo - kb, e = hi - kb;
    if (e < 0 || a > 31) return 0u;
    a = max(a, 0); e = min(e, 31);
    unsigned m = (e == 31) ? 0xFFFFFFFFu : ((1u << (e + 1)) - 1u);
    return m & (0xFFFFFFFFu << a);
}

__global__ void maskbuild_kernel() {
    int row = blockIdx.x;
    int b = row >> 11, q = row & (SS - 1);
    int w = threadIdx.x;
    int kb = w * 32;
    int win = g_WIN[row];
    unsigned m = range_word(max(q - win, 0), min(q + win, SS - 1), kb);
    if (g_HASKP[b]) {
        m |= g_KPB[row] ? 0xFFFFFFFFu : g_KPW[b * MWORDS + w];
    } else {
        unsigned fbw = ((w == 0) ? 1u : 0u) | (((w & 15) == 15) ? 0x80000000u : 0u);
        int qin = (q == 0 || q == 511 || q == 1023 || q == 1535 || q == 2047);
        m |= qin ? 0xFFFFFFFFu : fbw;
    }
    m |= g_CSW[b * MWORDS + w];
    g_MASK[(size_t)row * MWORDS + w] = m;
    int pc = __popc(m);
#pragma unroll
    for (int o = 16; o > 0; o >>= 1) pc += __shfl_down_sync(0xffffffffu, pc, o);
    __shared__ int ws[2];
    if ((w & 31) == 0) ws[w >> 5] = pc;
    __syncthreads();
    if (w == 0) atomicAdd(&g_COUNT[b], ws[0] + ws[1]);
}

// ---------------- needed ----------------
__global__ void needed_kernel() {
    if (threadIdx.x == 0) {
        float c0 = g_COMP[0], c1 = g_COMP[1];
        float mn = fminf(c0, c1), mx = fmaxf(c0, c1);
        for (int b = 0; b < BB; b++) {
            float nc = (g_COMP[b] - mn) / (mx - mn + 1e-6f);
            float ratio = fminf(fmaxf(0.3f * (0.5f + nc), 0.1f), 0.5f);
            float dens = (float)g_COUNT[b] / 4194304.0f;
            float nd = ceilf((ratio - dens) * 4194304.0f);
            int n = (int)nd;
            g_NEEDED[b] = max(n, 0);
        }
    }
}

// ---------------- random fill ----------------
__global__ void fill_kernel() {
    unsigned long long j = (unsigned long long)blockIdx.x * blockDim.x + threadIdx.x;
    if (j >= (unsigned long long)BB * NRAND) return;
    int b = (int)(j >> 21);
    int i = (int)(j & (NRAND - 1));
    if (i < g_NEEDED[b]) {
        unsigned qb = tf_bits(g_KEY_Q[0], g_KEY_Q[1], j, (unsigned long long)BB * NRAND);
        unsigned kb = tf_bits(g_KEY_K[0], g_KEY_K[1], j, (unsigned long long)BB * NRAND);
        int qr = qb & (SS - 1), kr = kb & (SS - 1);
        atomicOr(&g_MASK[((size_t)(b * SS + qr)) * MWORDS + (kr >> 5)], 1u << (kr & 31));
    }
}

// ---------------- flash attention with tf32 MMA ----------------
// block: 128 threads = 4 warps; each warp 16 q-rows; q-tile 64; k-tiles 64.
// smem (dyn): Ks[64*68] (tf32), Vs[64*72] (tf32), QPs[64*68] (Q staging, then P).
#define ATTN_SMEM_BYTES ((64*68 + 64*72 + 64*68) * 4)
__global__ void __launch_bounds__(128) attn_mma_kernel() {
    extern __shared__ unsigned smx[];
    unsigned* Ks  = smx;
    unsigned* Vs  = Ks + 64*68;
    unsigned* QPs = Vs + 64*72;
    int tid = threadIdx.x;
    int w = tid >> 5, lane = tid & 31;
    int g = lane >> 2, tig = lane & 3;
    int qt = blockIdx.x, bh = blockIdx.y;
    int b = bh >> 3, h = bh & 7;
    int q0 = qt * 64, wq = w * 16;
    size_t base_q = ((size_t)(b * SS + q0)) * DD + h * 64;

    // stage Q (pre-scaled by 1/8, tf32)
#pragma unroll
    for (int it = 0; it < 8; it++) {
        int idx = tid + it * 128;
        int r = idx >> 4, c4 = (idx & 15) << 2;
        float4 v = *(const float4*)(g_Qh + base_q + (size_t)r * DD + c4);
        QPs[r*68+c4+0] = f2tf32(v.x * 0.125f);
        QPs[r*68+c4+1] = f2tf32(v.y * 0.125f);
        QPs[r*68+c4+2] = f2tf32(v.z * 0.125f);
        QPs[r*68+c4+3] = f2tf32(v.w * 0.125f);
    }
    __syncthreads();
    int rl = (wq + g) * 68, rh = (wq + g + 8) * 68;
    unsigned qa[8][4];
#pragma unroll
    for (int ks = 0; ks < 8; ks++) {
        qa[ks][0] = QPs[rl + ks*8 + tig];
        qa[ks][1] = QPs[rh + ks*8 + tig];
        qa[ks][2] = QPs[rl + ks*8 + tig + 4];
        qa[ks][3] = QPs[rh + ks*8 + tig + 4];
    }
    float o[8][4];
#pragma unroll
    for (int nt = 0; nt < 8; nt++) { o[nt][0]=0; o[nt][1]=0; o[nt][2]=0; o[nt][3]=0; }
    float m_lo = -INFINITY, m_hi = -INFINITY, l_lo = 0.f, l_hi = 0.f;
    size_t qlo_row = (size_t)(b * SS + q0 + wq + g);
    size_t qhi_row = qlo_row + 8;
    const unsigned* mrow_lo = g_MASK + qlo_row * MWORDS;
    const unsigned* mrow_hi = g_MASK + qhi_row * MWORDS;

    for (int k0 = 0; k0 < SS; k0 += 64) {
        size_t base_k = ((size_t)(b * SS + k0)) * DD + h * 64;
#pragma unroll
        for (int it = 0; it < 8; it++) {
            int idx = tid + it * 128;
            int r = idx >> 4, c4 = (idx & 15) << 2;
            float4 kv = *(const float4*)(g_Kh + base_k + (size_t)r * DD + c4);
            float4 vv = *(const float4*)(g_Vh + base_k + (size_t)r * DD + c4);
            Ks[r*68+c4+0] = f2tf32(kv.x); Ks[r*68+c4+1] = f2tf32(kv.y);
            Ks[r*68+c4+2] = f2tf32(kv.z); Ks[r*68+c4+3] = f2tf32(kv.w);
            Vs[r*72+c4+0] = f2tf32(vv.x); Vs[r*72+c4+1] = f2tf32(vv.y);
            Vs[r*72+c4+2] = f2tf32(vv.z); Vs[r*72+c4+3] = f2tf32(vv.w);
        }
        __syncthreads();
        // S = (Q/8) K^T
        float s[8][4];
#pragma unroll
        for (int nt = 0; nt < 8; nt++) { s[nt][0]=0; s[nt][1]=0; s[nt][2]=0; s[nt][3]=0; }
#pragma unroll
        for (int ks = 0; ks < 8; ks++) {
#pragma unroll
            for (int nt = 0; nt < 8; nt++) {
                unsigned b0 = Ks[(nt*8+g)*68 + ks*8 + tig];
                unsigned b1 = Ks[(nt*8+g)*68 + ks*8 + tig + 4];
                mma_tf32(s[nt], qa[ks], b0, b1);
            }
        }
        // mask (bit set => masked OUT)
        unsigned ml0 = mrow_lo[k0 >> 5], ml1 = mrow_lo[(k0 >> 5) + 1];
        unsigned mh0 = mrow_hi[k0 >> 5], mh1 = mrow_hi[(k0 >> 5) + 1];
#pragma unroll
        for (int nt = 0; nt < 8; nt++) {
            int cb = nt*8 + 2*tig;
            unsigned wl = (cb < 32) ? ml0 : ml1;
            unsigned wh = (cb < 32) ? mh0 : mh1;
            int bit = cb & 31;
            if ((wl >> bit) & 1)       s[nt][0] = NEG_HUGE;
            if ((wl >> (bit + 1)) & 1) s[nt][1] = NEG_HUGE;
            if ((wh >> bit) & 1)       s[nt][2] = NEG_HUGE;
            if ((wh >> (bit + 1)) & 1) s[nt][3] = NEG_HUGE;
        }
        // online softmax
        float tm_lo = -INFINITY, tm_hi = -INFINITY;
#pragma unroll
        for (int nt = 0; nt < 8; nt++) {
            tm_lo = fmaxf(tm_lo, fmaxf(s[nt][0], s[nt][1]));
            tm_hi = fmaxf(tm_hi, fmaxf(s[nt][2], s[nt][3]));
        }
        tm_lo = fmaxf(tm_lo, __shfl_xor_sync(0xffffffffu, tm_lo, 1));
        tm_lo = fmaxf(tm_lo, __shfl_xor_sync(0xffffffffu, tm_lo, 2));
        tm_hi = fmaxf(tm_hi, __shfl_xor_sync(0xffffffffu, tm_hi, 1));
        tm_hi = fmaxf(tm_hi, __shfl_xor_sync(0xffffffffu, tm_hi, 2));
        float mn_lo = fmaxf(m_lo, tm_lo), mn_hi = fmaxf(m_hi, tm_hi);
        float sc_lo = __expf(m_lo - mn_lo), sc_hi = __expf(m_hi - mn_hi);
        m_lo = mn_lo; m_hi = mn_hi;
        float rs_lo = 0.f, rs_hi = 0.f;
#pragma unroll
        for (int nt = 0; nt < 8; nt++) {
            float p0 = __expf(s[nt][0] - m_lo);
            float p1 = __expf(s[nt][1] - m_lo);
            float p2 = __expf(s[nt][2] - m_hi);
            float p3 = __expf(s[nt][3] - m_hi);
            rs_lo += p0 + p1; rs_hi += p2 + p3;
            *(uint2*)&QPs[rl + nt*8 + 2*tig] = make_uint2(f2tf32(p0), f2tf32(p1));
            *(uint2*)&QPs[rh + nt*8 + 2*tig] = make_uint2(f2tf32(p2), f2tf32(p3));
            o[nt][0] *= sc_lo; o[nt][1] *= sc_lo; o[nt][2] *= sc_hi; o[nt][3] *= sc_hi;
        }
        rs_lo += __shfl_xor_sync(0xffffffffu, rs_lo, 1);
        rs_lo += __shfl_xor_sync(0xffffffffu, rs_lo, 2);
        rs_hi += __shfl_xor_sync(0xffffffffu, rs_hi, 1);
        rs_hi += __shfl_xor_sync(0xffffffffu, rs_hi, 2);
        l_lo = l_lo * sc_lo + rs_lo;
        l_hi = l_hi * sc_hi + rs_hi;
        __syncwarp();
        // O += P V
#pragma unroll
        for (int ks = 0; ks < 8; ks++) {
            unsigned pa[4];
            pa[0] = QPs[rl + ks*8 + tig];
            pa[1] = QPs[rh + ks*8 + tig];
            pa[2] = QPs[rl + ks*8 + tig + 4];
            pa[3] = QPs[rh + ks*8 + tig + 4];
#pragma unroll
            for (int nt = 0; nt < 8; nt++) {
                unsigned b0 = Vs[(ks*8+tig)*72 + nt*8 + g];
                unsigned b1 = Vs[(ks*8+tig+4)*72 + nt*8 + g];
                mma_tf32(o[nt], pa, b0, b1);
            }
        }
        __syncthreads();
    }
    float il = 1.f / l_lo, ih = 1.f / l_hi;
    size_t obase_lo = qlo_row * DD + h * 64;
    size_t obase_hi = qhi_row * DD + h * 64;
#pragma unroll
    for (int nt = 0; nt < 8; nt++) {
        int c = nt*8 + 2*tig;
        *(float2*)(g_CTX + obase_lo + c) = make_float2(o[nt][0]*il, o[nt][1]*il);
        *(float2*)(g_CTX + obase_hi + c) = make_float2(o[nt][2]*ih, o[nt][3]*ih);
    }
}

// ---------------- launch ----------------
extern "C" void kernel_launch(void* const* d_in, const int* in_sizes, int n_in,
                              void* d_out, int out_size) {
    const float* queries = (const float*)d_in[0];
    const float* keys    = (const float*)d_in[1];
    const float* values  = (const float*)d_in[2];
    const float* ln_q_g  = (const float*)d_in[3];
    const float* ln_q_b  = (const float*)d_in[4];
    const float* ln_k_g  = (const float*)d_in[5];
    const float* ln_k_b  = (const float*)d_in[6];
    const float* ln_v_g  = (const float*)d_in[7];
    const float* ln_v_b  = (const float*)d_in[8];
    const float* Wq = (const float*)d_in[9];   const float* bq = (const float*)d_in[10];
    const float* Wk = (const float*)d_in[11];  const float* bk = (const float*)d_in[12];
    const float* Wv = (const float*)d_in[13];  const float* bv = (const float*)d_in[14];
    const float* Wo = (const float*)d_in[15];  const float* bo = (const float*)d_in[16];
    const float* Ww1 = (const float*)d_in[17]; const float* bw1 = (const float*)d_in[18];
    const float* Ww2 = (const float*)d_in[19]; const float* bw2 = (const float*)d_in[20];
    float* out = (float*)d_out;

    float *QN, *KN, *VN, *Qh, *Kh, *Vh, *CTX, *HID;
    cudaGetSymbolAddress((void**)&QN, g_QN);
    cudaGetSymbolAddress((void**)&KN, g_KN);
    cudaGetSymbolAddress((void**)&VN, g_VN);
    cudaGetSymbolAddress((void**)&Qh, g_Qh);
    cudaGetSymbolAddress((void**)&Kh, g_Kh);
    cudaGetSymbolAddress((void**)&Vh, g_Vh);
    cudaGetSymbolAddress((void**)&CTX, g_CTX);
    cudaGetSymbolAddress((void**)&HID, g_HID);

    init_kernel<<<1, 128>>>();
    ln_warp_kernel<<<NROWS/8, 256>>>(queries, ln_q_g, ln_q_b, QN, 1);
    ln_warp_kernel<<<NROWS/8, 256>>>(keys,    ln_k_g, ln_k_b, KN, 0);
    ln_warp_kernel<<<NROWS/8, 256>>>(values,  ln_v_g, ln_v_b, VN, 0);

    // window MLP hidden (fp32 — rintf-sensitive path)
    gemm_kernel<<<dim3(2, 64), 256>>>(QN, Ww1, bw1, nullptr, HID, 128, 1);
    winred_kernel<<<NROWS, 128>>>(Ww2, bw2);

    dm_kernel<<<NROWS, 256>>>();
    batchstat_kernel<<<BB, 1024>>>();
    kp_kernel<<<BB, 1024>>>();
    gumbel_kernel<<<BB * 4, 512>>>();
    maskbuild_kernel<<<NROWS, 64>>>();
    needed_kernel<<<1, 32>>>();
    fill_kernel<<<(BB * NRAND) / 256, 256>>>();

    // projections (tf32 MMA)
    gemm_mma_kernel<<<dim3(8, 64), 128>>>(QN, Wq, bq, nullptr, Qh, 512);
    gemm_mma_kernel<<<dim3(8, 64), 128>>>(KN, Wk, bk, nullptr, Kh, 512);
    gemm_mma_kernel<<<dim3(8, 64), 128>>>(VN, Wv, bv, nullptr, Vh, 512);

    // attention (tf32 MMA flash)
    cudaFuncSetAttribute(attn_mma_kernel, cudaFuncAttributeMaxDynamicSharedMemorySize,
                         ATTN_SMEM_BYTES);
    attn_mma_kernel<<<dim3(SS / 64, BB * HH), 128, ATTN_SMEM_BYTES>>>();

    // output projection + residual (tf32 MMA)
    gemm_mma_kernel<<<dim3(8, 64), 128>>>(CTX, Wo, bo, queries, out, 512);
}

// round 7
// speedup vs baseline: 2.4599x; 1.1793x over previous
#include <cuda_runtime.h>
#include <cuda_bf16.h>
#include <cuda_fp16.h>
#include <math.h>
#include <stdint.h>

// ---------------- problem constants ----------------
#define BB 2
#define SS 2048
#define DD 512
#define HH 8
#define NROWS (BB*SS)            // 4096
#define MWORDS (SS/32)           // 64
#define NRAND (SS*SS/2)          // 2097152 (power of two)
#define NEG_HUGE (-3.4028234663852886e38f)
#define TINYF 1.17549435e-38f

#define TF_PARTITIONABLE 1

// ---------------- scratch (device globals; no runtime alloc) ----------------
__device__ float g_QN[NROWS*DD];
__device__ float g_KN[NROWS*DD];
__device__ float g_VN[NROWS*DD];
__device__ float g_Qh[NROWS*DD];
__device__ float g_Kh[NROWS*DD];
__device__ float g_Vh[NROWS*DD];
__device__ float g_CTX[NROWS*DD];
__device__ float g_HID[NROWS*128];
__device__ unsigned g_MASK[NROWS*MWORDS];
__device__ float g_DM[NROWS], g_CH[NROWS], g_MAG[NROWS], g_VAR1[NROWS], g_IMP[NROWS];
__device__ int   g_WIN[NROWS];
__device__ unsigned char g_KPB[NROWS];
__device__ unsigned g_KPW[BB*MWORDS];
__device__ unsigned g_CSW[BB*MWORDS];
__device__ float g_THR[BB], g_COMP[BB], g_IMPLO[BB], g_IMPHI[BB];
__device__ int   g_HASKP[BB], g_COUNT[BB], g_NEEDED[BB];
__device__ unsigned g_KEY_G[2], g_KEY_Q[2], g_KEY_K[2];

// ---------------- threefry-2x32 (JAX 20-round) ----------------
__device__ __forceinline__ void tf2x32(unsigned k0, unsigned k1, unsigned x0, unsigned x1,
                                       unsigned &o0, unsigned &o1) {
    unsigned ks2 = k0 ^ k1 ^ 0x1BD11BDAu;
    x0 += k0; x1 += k1;
#define TFR(r) { x0 += x1; x1 = (x1 << r) | (x1 >> (32 - r)); x1 ^= x0; }
    TFR(13) TFR(15) TFR(26) TFR(6)
    x0 += k1;  x1 += ks2 + 1u;
    TFR(17) TFR(29) TFR(16) TFR(24)
    x0 += ks2; x1 += k0 + 2u;
    TFR(13) TFR(15) TFR(26) TFR(6)
    x0 += k0;  x1 += k1 + 3u;
    TFR(17) TFR(29) TFR(16) TFR(24)
    x0 += k1;  x1 += ks2 + 4u;
    TFR(13) TFR(15) TFR(26) TFR(6)
    x0 += ks2; x1 += k0 + 5u;
#undef TFR
    o0 = x0; o1 = x1;
}

__device__ __forceinline__ unsigned tf_bits(unsigned k0, unsigned k1,
                                            unsigned long long idx,
                                            unsigned long long total) {
#if TF_PARTITIONABLE
    unsigned o0, o1;
    tf2x32(k0, k1, (unsigned)(idx >> 32), (unsigned)idx, o0, o1);
    return o0 ^ o1;
#else
    unsigned long long half = (total + 1ull) / 2ull;
    unsigned o0, o1;
    if (idx < half) { tf2x32(k0, k1, (unsigned)idx, (unsigned)(idx + half), o0, o1); return o0; }
    else            { tf2x32(k0, k1, (unsigned)(idx - half), (unsigned)idx, o0, o1); return o1; }
#endif
}

// ---------------- fp16 MMA helper ----------------
__device__ __forceinline__ void mma_f16(float d[4], const unsigned a[4],
                                        unsigned b0, unsigned b1) {
    asm volatile("mma.sync.aligned.m16n8k16.row.col.f32.f16.f16.f32 "
        "{%0,%1,%2,%3}, {%4,%5,%6,%7}, {%8,%9}, {%0,%1,%2,%3};"
        : "+f"(d[0]), "+f"(d[1]), "+f"(d[2]), "+f"(d[3])
        : "r"(a[0]), "r"(a[1]), "r"(a[2]), "r"(a[3]), "r"(b0), "r"(b1));
}
__device__ __forceinline__ unsigned h2u(__half2 h) { return *(unsigned*)&h; }

// ---------------- block reductions ----------------
__device__ __forceinline__ float bredSum(float v, float* s, int n) {
    int t = threadIdx.x; s[t] = v; __syncthreads();
    for (int k = n >> 1; k > 0; k >>= 1) { if (t < k) s[t] += s[t + k]; __syncthreads(); }
    float r = s[0]; __syncthreads(); return r;
}
__device__ __forceinline__ float bredMax(float v, float* s, int n) {
    int t = threadIdx.x; s[t] = v; __syncthreads();
    for (int k = n >> 1; k > 0; k >>= 1) { if (t < k) s[t] = fmaxf(s[t], s[t + k]); __syncthreads(); }
    float r = s[0]; __syncthreads(); return r;
}
__device__ __forceinline__ float bredMin(float v, float* s, int n) {
    int t = threadIdx.x; s[t] = v; __syncthreads();
    for (int k = n >> 1; k > 0; k >>= 1) { if (t < k) s[t] = fminf(s[t], s[t + k]); __syncthreads(); }
    float r = s[0]; __syncthreads(); return r;
}

// ---------------- init ----------------
__global__ void init_kernel() {
    int t = blockIdx.x * blockDim.x + threadIdx.x;
    if (t < BB*MWORDS) g_CSW[t] = 0u;
    if (t < BB) g_COUNT[t] = 0;
    if (t == 0) {
        unsigned o0, o1, a0, a1;
        tf2x32(0u, 42u, 0u, 0u, o0, o1); g_KEY_G[0] = o0; g_KEY_G[1] = o1;
#if TF_PARTITIONABLE
        tf2x32(0u, 42u, 0u, 1u, o0, o1);
        tf2x32(o0, o1, 0u, 1u, a0, a1); g_KEY_Q[0] = a0; g_KEY_Q[1] = a1;
        tf2x32(0u, 42u, 0u, 2u, o0, o1);
        tf2x32(o0, o1, 0u, 1u, a0, a1); g_KEY_K[0] = a0; g_KEY_K[1] = a1;
#else
        unsigned p0, p1, q0, q1;
        tf2x32(0u, 42u, 0u, 1u, o0, o1);
        tf2x32(o0, o1, 0u, 2u, p0, p1);
        tf2x32(o0, o1, 1u, 3u, q0, q1);
        g_KEY_Q[0] = p1; g_KEY_Q[1] = q1;
        tf2x32(0u, 42u, 0u, 2u, o0, o1);
        tf2x32(o0, o1, 0u, 2u, p0, p1);
        tf2x32(o0, o1, 1u, 3u, q0, q1);
        g_KEY_K[0] = p1; g_KEY_K[1] = q1;
#endif
    }
}

// ---------------- warp-per-row LayerNorm (+qn stats) ----------------
__global__ void ln_warp_kernel(const float* __restrict__ x, const float* __restrict__ gam,
                               const float* __restrict__ bet, float* __restrict__ y, int stats) {
    int w = threadIdx.x >> 5, lane = threadIdx.x & 31;
    int row = blockIdx.x * 8 + w;
    const float4* xr = (const float4*)(x + (size_t)row * 512);
    float4 v[4];
#pragma unroll
    for (int j = 0; j < 4; j++) v[j] = xr[lane + j * 32];
    float s = 0.f;
#pragma unroll
    for (int j = 0; j < 4; j++) s += v[j].x + v[j].y + v[j].z + v[j].w;
#pragma unroll
    for (int o = 16; o > 0; o >>= 1) s += __shfl_xor_sync(0xffffffffu, s, o);
    float mu = s * (1.f / 512.f);
    float qv = 0.f;
#pragma unroll
    for (int j = 0; j < 4; j++) {
        float a = v[j].x - mu, b = v[j].y - mu, c = v[j].z - mu, d = v[j].w - mu;
        qv += a * a + b * b + c * c + d * d;
    }
#pragma unroll
    for (int o = 16; o > 0; o >>= 1) qv += __shfl_xor_sync(0xffffffffu, qv, o);
    float r = rsqrtf(qv * (1.f / 512.f) + 1e-5f);
    const float4* g4 = (const float4*)gam;
    const float4* b4 = (const float4*)bet;
    float4* yr = (float4*)(y + (size_t)row * 512);
    float yv[16];
#pragma unroll
    for (int j = 0; j < 4; j++) {
        float4 gg = g4[lane + j * 32], bb = b4[lane + j * 32];
        float4 o4;
        o4.x = (v[j].x - mu) * r * gg.x + bb.x;
        o4.y = (v[j].y - mu) * r * gg.y + bb.y;
        o4.z = (v[j].z - mu) * r * gg.z + bb.z;
        o4.w = (v[j].w - mu) * r * gg.w + bb.w;
        yr[lane + j * 32] = o4;
        yv[j*4+0] = o4.x; yv[j*4+1] = o4.y; yv[j*4+2] = o4.z; yv[j*4+3] = o4.w;
    }
    if (stats) {
        float sq = 0.f, sy = 0.f;
#pragma unroll
        for (int i = 0; i < 16; i++) { sq += yv[i] * yv[i]; sy += yv[i]; }
#pragma unroll
        for (int o = 16; o > 0; o >>= 1) {
            sq += __shfl_xor_sync(0xffffffffu, sq, o);
            sy += __shfl_xor_sync(0xffffffffu, sy, o);
        }
        float my = sy * (1.f / 512.f);
        float sd = 0.f;
#pragma unroll
        for (int i = 0; i < 16; i++) { float e = yv[i] - my; sd += e * e; }
#pragma unroll
        for (int o = 16; o > 0; o >>= 1) sd += __shfl_xor_sync(0xffffffffu, sd, o);
        if (lane == 0) { g_MAG[row] = sqrtf(sq); g_VAR1[row] = sd * (1.f / 511.f); }
    }
}

// ---------------- fp32 GEMM (window-MLP hidden only; rintf-sensitive) ---------
__global__ void gemm_kernel(const float* __restrict__ A, const float* __restrict__ W,
                            const float* __restrict__ bias, const float* __restrict__ resid,
                            float* __restrict__ C, int N, int doRelu) {
    __shared__ float As[64][17];
    __shared__ float Ws[64][17];
    int row0 = blockIdx.y * 64;
    int col0 = blockIdx.x * 64;
    int tid = threadIdx.x;
    int tx = tid & 15, ty = tid >> 4;
    int r0 = ty * 4, c0 = tx * 4;
    int lr = tid >> 2, lc4 = (tid & 3) * 4;
    float acc[4][4] = {};
    for (int kk = 0; kk < 512; kk += 16) {
        float4 av = *reinterpret_cast<const float4*>(A + (size_t)(row0 + lr) * 512 + kk + lc4);
        float4 wv = *reinterpret_cast<const float4*>(W + (size_t)(col0 + lr) * 512 + kk + lc4);
        As[lr][lc4] = av.x; As[lr][lc4+1] = av.y; As[lr][lc4+2] = av.z; As[lr][lc4+3] = av.w;
        Ws[lr][lc4] = wv.x; Ws[lr][lc4+1] = wv.y; Ws[lr][lc4+2] = wv.z; Ws[lr][lc4+3] = wv.w;
        __syncthreads();
#pragma unroll
        for (int kc = 0; kc < 16; kc++) {
            float a0 = As[r0][kc], a1 = As[r0+1][kc], a2 = As[r0+2][kc], a3 = As[r0+3][kc];
            float b0 = Ws[c0][kc], b1 = Ws[c0+1][kc], b2 = Ws[c0+2][kc], b3 = Ws[c0+3][kc];
            acc[0][0] += a0*b0; acc[0][1] += a0*b1; acc[0][2] += a0*b2; acc[0][3] += a0*b3;
            acc[1][0] += a1*b0; acc[1][1] += a1*b1; acc[1][2] += a1*b2; acc[1][3] += a1*b3;
            acc[2][0] += a2*b0; acc[2][1] += a2*b1; acc[2][2] += a2*b2; acc[2][3] += a2*b3;
            acc[3][0] += a3*b0; acc[3][1] += a3*b1; acc[3][2] += a3*b2; acc[3][3] += a3*b3;
        }
        __syncthreads();
    }
#pragma unroll
    for (int i = 0; i < 4; i++) {
#pragma unroll
        for (int j = 0; j < 4; j++) {
            int col = col0 + c0 + j;
            size_t ro = (size_t)(row0 + r0 + i);
            float v = acc[i][j] + bias[col];
            if (doRelu) v = fmaxf(v, 0.f);
            if (resid) v += resid[ro * (size_t)N + col];
            C[ro * (size_t)N + col] = v;
        }
    }
}

// ---------------- fp16 MMA GEMM: C[4096][N] = A[4096][512] @ W[N][512]^T + b ----
#define GS 40   // smem row stride in halves for 32-k chunk
__global__ void __launch_bounds__(128) gemm_h_kernel(
        const float* __restrict__ A, const float* __restrict__ W,
        const float* __restrict__ bias, const float* __restrict__ resid,
        float* __restrict__ C, int N) {
    __shared__ __half As[64*GS];
    __shared__ __half Ws[64*GS];
    int tid = threadIdx.x;
    int w = tid >> 5, lane = tid & 31, g = lane >> 2, tig = lane & 3;
    int col0 = blockIdx.x * 64, row0 = blockIdx.y * 64;
    int wq = w * 16;
    float acc[8][4];
#pragma unroll
    for (int nt = 0; nt < 8; nt++) { acc[nt][0]=0; acc[nt][1]=0; acc[nt][2]=0; acc[nt][3]=0; }
    for (int kc = 0; kc < 512; kc += 32) {
#pragma unroll
        for (int it = 0; it < 4; it++) {
            int idx = tid + it * 128;
            int r = idx >> 3, c4 = (idx & 7) << 2;
            float4 av = *(const float4*)(A + (size_t)(row0 + r) * 512 + kc + c4);
            float4 wv = *(const float4*)(W + (size_t)(col0 + r) * 512 + kc + c4);
            __half2 a01 = __floats2half2_rn(av.x, av.y);
            __half2 a23 = __floats2half2_rn(av.z, av.w);
            __half2 w01 = __floats2half2_rn(wv.x, wv.y);
            __half2 w23 = __floats2half2_rn(wv.z, wv.w);
            *(uint2*)&As[r*GS + c4] = make_uint2(h2u(a01), h2u(a23));
            *(uint2*)&Ws[r*GS + c4] = make_uint2(h2u(w01), h2u(w23));
        }
        __syncthreads();
#pragma unroll
        for (int ks = 0; ks < 2; ks++) {
            unsigned a[4];
            a[0] = *(unsigned*)&As[(wq+g)*GS   + ks*16 + 2*tig];
            a[1] = *(unsigned*)&As[(wq+g+8)*GS + ks*16 + 2*tig];
            a[2] = *(unsigned*)&As[(wq+g)*GS   + ks*16 + 8 + 2*tig];
            a[3] = *(unsigned*)&As[(wq+g+8)*GS + ks*16 + 8 + 2*tig];
#pragma unroll
            for (int nt = 0; nt < 8; nt++) {
                unsigned b0 = *(unsigned*)&Ws[(nt*8+g)*GS + ks*16 + 2*tig];
                unsigned b1 = *(unsigned*)&Ws[(nt*8+g)*GS + ks*16 + 8 + 2*tig];
                mma_f16(acc[nt], a, b0, b1);
            }
        }
        __syncthreads();
    }
    int rlo = row0 + wq + g, rhi = rlo + 8;
#pragma unroll
    for (int nt = 0; nt < 8; nt++) {
        int c = col0 + nt*8 + 2*tig;
        float v0 = acc[nt][0] + bias[c],   v1 = acc[nt][1] + bias[c+1];
        float v2 = acc[nt][2] + bias[c],   v3 = acc[nt][3] + bias[c+1];
        if (resid) {
            v0 += resid[(size_t)rlo * N + c];   v1 += resid[(size_t)rlo * N + c + 1];
            v2 += resid[(size_t)rhi * N + c];   v3 += resid[(size_t)rhi * N + c + 1];
        }
        C[(size_t)rlo * N + c] = v0; C[(size_t)rlo * N + c + 1] = v1;
        C[(size_t)rhi * N + c] = v2; C[(size_t)rhi * N + c + 1] = v3;
    }
}

// ---------------- window reduce ----------------
__global__ void winred_kernel(const float* __restrict__ W2, const float* __restrict__ b2) {
    __shared__ float sb[128];
    int row = blockIdx.x, tid = threadIdx.x;
    sb[tid] = g_HID[(size_t)row * 128 + tid] * W2[tid];
    __syncthreads();
    for (int st = 64; st > 0; st >>= 1) { if (tid < st) sb[tid] += sb[tid + st]; __syncthreads(); }
    if (tid == 0) {
        float s = sb[0] + b2[0];
        float adj = 0.5f + 1.0f / (1.0f + expf(-s));
        int w = (int)rintf(64.0f * adj);
        g_WIN[row] = min(max(w, 1), 128);
    }
}

// ---------------- dm/ch/imp ----------------
__global__ void dm_kernel() {
    __shared__ float sb[256];
    int row = blockIdx.x, tid = threadIdx.x;
    int t = row & (SS - 1);
    const float* q0 = g_QN + (size_t)row * DD;
    float acc = 0.f, chs = 0.f;
    const int   sv[4] = {1, 2, 3, 5};
    const float wv[4] = {0.4f, 0.3f, 0.2f, 0.1f};
    for (int l = 0; l < 2; l++) {
        int d = tid + l * 256;
        float base = q0[d];
#pragma unroll
        for (int si = 0; si < 4; si++) {
            int s = sv[si];
            if (t + s < SS)
                acc += wv[si] * (fabsf(q0[(size_t)s * DD + d] - base) / (float)s);
        }
        if (t < SS - 1) chs += fabsf(q0[DD + d] - base);
    }
    float a = bredSum(acc, sb, 256);
    float c = bredSum(chs, sb, 256);
    if (tid == 0) {
        float chv = c * (1.f / 512.f);
        g_DM[row] = a * (1.f / 512.f);
        g_CH[row] = chv;
        g_IMP[row] = 0.5f * g_MAG[row] + 0.5f * chv;
    }
}

// ---------------- per-batch stats ----------------
__global__ void batchstat_kernel() {
    __shared__ float sb[1024];
    int b = blockIdx.x, tid = threadIdx.x;
    int r0 = b * SS + tid, r1 = r0 + 1024;
    float d0 = g_DM[r0], d1 = g_DM[r1];
    float mean = bredSum(d0 + d1, sb, 1024) * (1.f / 2048.f);
    float e0 = d0 - mean, e1 = d1 - mean;
    float var = bredSum(e0 * e0 + e1 * e1, sb, 1024) * (1.f / 2047.f);
    float comp = bredSum(g_VAR1[r0] + g_VAR1[r1], sb, 1024) * (1.f / 2048.f);
    float i0 = g_IMP[r0], i1 = g_IMP[r1];
    float lo = bredMin(fminf(i0, i1), sb, 1024);
    float hi = bredMax(fmaxf(i0, i1), sb, 1024);
    if (tid == 0) {
        g_THR[b] = mean + 0.5f * sqrtf(var);
        g_COMP[b] = comp;
        g_IMPLO[b] = lo; g_IMPHI[b] = hi;
    }
}

// ---------------- keypoints ----------------
__global__ void kp_kernel() {
    __shared__ unsigned char kpf[SS];
    __shared__ int anyf;
    int b = blockIdx.x, tid = threadIdx.x;
    if (tid == 0) anyf = 0;
    __syncthreads();
    float thr = g_THR[b];
    for (int it = 0; it < 2; it++) {
        int t = tid + it * 1024;
        int row = b * SS + t;
        float dm = g_DM[row];
        float left  = (t > 0)      ? g_DM[row - 1] : -1.0f;
        float right = (t < SS - 1) ? g_DM[row + 1] : -1.0f;
        int kp = (dm > thr) && (dm > left) && (dm > right);
        if (t == 0 || t == SS - 1) kp = kp || (dm > thr);
        kpf[t] = (unsigned char)kp;
        g_KPB[row] = (unsigned char)kp;
        if (kp) anyf = 1;
    }
    __syncthreads();
    if (tid < MWORDS) {
        unsigned w = 0;
        for (int j = 0; j < 32; j++) if (kpf[tid * 32 + j]) w |= (1u << j);
        g_KPW[b * MWORDS + tid] = w;
    }
    if (tid == 0) g_HASKP[b] = anyf;
}

// ---------------- stratified gumbel top-4 ----------------
__global__ void gumbel_kernel() {
    __shared__ float sb[512];
    __shared__ float lv[512];
    __shared__ int si[512];
    int seg = blockIdx.x;
    int b = seg >> 2, l = seg & 3;
    int tid = threadIdx.x;
    int t = l * 512 + tid;
    int row = b * SS + t;
    float lo = g_IMPLO[b], hi = g_IMPHI[b];
    float ip = (g_IMP[row] - lo) / (hi - lo + 1e-6f);
    float ssum = bredSum(ip, sb, 512);
    float prob = ip / (ssum + 1e-6f);
    unsigned bits = tf_bits(g_KEY_G[0], g_KEY_G[1], (unsigned long long)(seg * 512 + tid), 4096ull);
    float f = __uint_as_float((bits >> 9) | 0x3f800000u) - 1.0f;
    float u = fmaxf(TINYF, f * (1.0f - TINYF) + TINYF);
    float gum = -logf(-logf(u));
    lv[tid] = logf(prob + 1e-20f) + gum;
    __syncthreads();
    for (int round = 0; round < 4; round++) {
        sb[tid] = lv[tid]; si[tid] = tid;
        __syncthreads();
        for (int st = 256; st > 0; st >>= 1) {
            if (tid < st) {
                float ov = sb[tid + st]; int oi = si[tid + st];
                if (ov > sb[tid] || (ov == sb[tid] && oi < si[tid])) { sb[tid] = ov; si[tid] = oi; }
            }
            __syncthreads();
        }
        if (tid == 0) {
            int sel = si[0];
            int tt = l * 512 + sel;
            atomicOr(&g_CSW[b * MWORDS + (tt >> 5)], 1u << (tt & 31));
            lv[sel] = -INFINITY;
        }
        __syncthreads();
    }
}

// ---------------- mask build + density ----------------
__device__ __forceinline__ unsigned range_word(int lo, int hi, int kb) {
    int a = lo - kb, e = hi - kb;
    if (e < 0 || a > 31) return 0u;
    a = max(a, 0); e = min(e, 31);
    unsigned m = (e == 31) ? 0xFFFFFFFFu : ((1u << (e + 1)) - 1u);
    return m & (0xFFFFFFFFu << a);
}

__global__ void maskbuild_kernel() {
    int row = blockIdx.x;
    int b = row >> 11, q = row & (SS - 1);
    int w = threadIdx.x;
    int kb = w * 32;
    int win = g_WIN[row];
    unsigned m = range_word(max(q - win, 0), min(q + win, SS - 1), kb);
    if (g_HASKP[b]) {
        m |= g_KPB[row] ? 0xFFFFFFFFu : g_KPW[b * MWORDS + w];
    } else {
        unsigned fbw = ((w == 0) ? 1u : 0u) | (((w & 15) == 15) ? 0x80000000u : 0u);
        int qin = (q == 0 || q == 511 || q == 1023 || q == 1535 || q == 2047);
        m |= qin ? 0xFFFFFFFFu : fbw;
    }
    m |= g_CSW[b * MWORDS + w];
    g_MASK[(size_t)row * MWORDS + w] = m;
    int pc = __popc(m);
#pragma unroll
    for (int o = 16; o > 0; o >>= 1) pc += __shfl_down_sync(0xffffffffu, pc, o);
    __shared__ int ws[2];
    if ((w & 31) == 0) ws[w >> 5] = pc;
    __syncthreads();
    if (w == 0) atomicAdd(&g_COUNT[b], ws[0] + ws[1]);
}

// ---------------- needed ----------------
__global__ void needed_kernel() {
    if (threadIdx.x == 0) {
        float c0 = g_COMP[0], c1 = g_COMP[1];
        float mn = fminf(c0, c1), mx = fmaxf(c0, c1);
        for (int b = 0; b < BB; b++) {
            float nc = (g_COMP[b] - mn) / (mx - mn + 1e-6f);
            float ratio = fminf(fmaxf(0.3f * (0.5f + nc), 0.1f), 0.5f);
            float dens = (float)g_COUNT[b] / 4194304.0f;
            float nd = ceilf((ratio - dens) * 4194304.0f);
            int n = (int)nd;
            g_NEEDED[b] = max(n, 0);
        }
    }
}

// ---------------- random fill ----------------
__global__ void fill_kernel() {
    unsigned long long j = (unsigned long long)blockIdx.x * blockDim.x + threadIdx.x;
    if (j >= (unsigned long long)BB * NRAND) return;
    int b = (int)(j >> 21);
    int i = (int)(j & (NRAND - 1));
    if (i < g_NEEDED[b]) {
        unsigned qb = tf_bits(g_KEY_Q[0], g_KEY_Q[1], j, (unsigned long long)BB * NRAND);
        unsigned kb = tf_bits(g_KEY_K[0], g_KEY_K[1], j, (unsigned long long)BB * NRAND);
        int qr = qb & (SS - 1), kr = kb & (SS - 1);
        atomicOr(&g_MASK[((size_t)(b * SS + qr)) * MWORDS + (kr >> 5)], 1u << (kr & 31));
    }
}

// ---------------- flash attention with fp16 MMA (m16n8k16) ----------------
// 128 threads = 4 warps, 16 q-rows each; q-tile 64, k-tile 64.
// Ks[key][d] half; VT[d][key] half (transposed so PV B-frags are contiguous);
// Qs[row][d] half (scaled by 1/8). P stays in registers (S-accum layout == A-frag layout).
#define AT_STR 72
__global__ void __launch_bounds__(128) attn_h_kernel() {
    __shared__ __half Ks[64*AT_STR];
    __shared__ __half VT[64*AT_STR];
    __shared__ __half Qs[64*AT_STR];
    int tid = threadIdx.x;
    int w = tid >> 5, lane = tid & 31;
    int g = lane >> 2, tig = lane & 3;
    int qt = blockIdx.x, bh = blockIdx.y;
    int b = bh >> 3, h = bh & 7;
    int q0 = qt * 64, wq = w * 16;
    size_t base_q = ((size_t)(b * SS + q0)) * DD + h * 64;

    // stage Q (scaled 1/8, fp16)
#pragma unroll
    for (int it = 0; it < 8; it++) {
        int idx = tid + it * 128;
        int r = idx >> 4, c4 = (idx & 15) << 2;
        float4 v = *(const float4*)(g_Qh + base_q + (size_t)r * DD + c4);
        __half2 h01 = __floats2half2_rn(v.x * 0.125f, v.y * 0.125f);
        __half2 h23 = __floats2half2_rn(v.z * 0.125f, v.w * 0.125f);
        *(uint2*)&Qs[r*AT_STR + c4] = make_uint2(h2u(h01), h2u(h23));
    }
    __syncthreads();
    int rl = (wq + g) * AT_STR, rh = (wq + g + 8) * AT_STR;
    unsigned qa[4][4];
#pragma unroll
    for (int ks = 0; ks < 4; ks++) {
        qa[ks][0] = *(unsigned*)&Qs[rl + ks*16 + 2*tig];
        qa[ks][1] = *(unsigned*)&Qs[rh + ks*16 + 2*tig];
        qa[ks][2] = *(unsigned*)&Qs[rl + ks*16 + 8 + 2*tig];
        qa[ks][3] = *(unsigned*)&Qs[rh + ks*16 + 8 + 2*tig];
    }
    float o[8][4];
#pragma unroll
    for (int nt = 0; nt < 8; nt++) { o[nt][0]=0; o[nt][1]=0; o[nt][2]=0; o[nt][3]=0; }
    float m_lo = -INFINITY, m_hi = -INFINITY, l_lo = 0.f, l_hi = 0.f;
    size_t qlo_row = (size_t)(b * SS + q0 + wq + g);
    size_t qhi_row = qlo_row + 8;
    const unsigned* mrow_lo = g_MASK + qlo_row * MWORDS;
    const unsigned* mrow_hi = g_MASK + qhi_row * MWORDS;

    for (int k0 = 0; k0 < SS; k0 += 64) {
        size_t base_k = ((size_t)(b * SS + k0)) * DD + h * 64;
        __syncthreads();   // protect smem from previous iteration's readers
#pragma unroll
        for (int it = 0; it < 8; it++) {
            int idx = tid + it * 128;
            int r = idx >> 4, c4 = (idx & 15) << 2;
            float4 kv = *(const float4*)(g_Kh + base_k + (size_t)r * DD + c4);
            float4 vv = *(const float4*)(g_Vh + base_k + (size_t)r * DD + c4);
            __half2 k01 = __floats2half2_rn(kv.x, kv.y);
            __half2 k23 = __floats2half2_rn(kv.z, kv.w);
            *(uint2*)&Ks[r*AT_STR + c4] = make_uint2(h2u(k01), h2u(k23));
            VT[(c4+0)*AT_STR + r] = __float2half_rn(vv.x);
            VT[(c4+1)*AT_STR + r] = __float2half_rn(vv.y);
            VT[(c4+2)*AT_STR + r] = __float2half_rn(vv.z);
            VT[(c4+3)*AT_STR + r] = __float2half_rn(vv.w);
        }
        __syncthreads();
        // S = (Q/8) K^T
        float s[8][4];
#pragma unroll
        for (int nt = 0; nt < 8; nt++) { s[nt][0]=0; s[nt][1]=0; s[nt][2]=0; s[nt][3]=0; }
#pragma unroll
        for (int ks = 0; ks < 4; ks++) {
#pragma unroll
            for (int nt = 0; nt < 8; nt++) {
                unsigned b0 = *(unsigned*)&Ks[(nt*8+g)*AT_STR + ks*16 + 2*tig];
                unsigned b1 = *(unsigned*)&Ks[(nt*8+g)*AT_STR + ks*16 + 8 + 2*tig];
                mma_f16(s[nt], qa[ks], b0, b1);
            }
        }
        // mask (bit set => masked OUT)
        unsigned ml0 = mrow_lo[k0 >> 5], ml1 = mrow_lo[(k0 >> 5) + 1];
        unsigned mh0 = mrow_hi[k0 >> 5], mh1 = mrow_hi[(k0 >> 5) + 1];
#pragma unroll
        for (int nt = 0; nt < 8; nt++) {
            int cb = nt*8 + 2*tig;
            unsigned wl = (cb < 32) ? ml0 : ml1;
            unsigned wh = (cb < 32) ? mh0 : mh1;
            int bit = cb & 31;
            if ((wl >> bit) & 1)       s[nt][0] = NEG_HUGE;
            if ((wl >> (bit + 1)) & 1) s[nt][1] = NEG_HUGE;
            if ((wh >> bit) & 1)       s[nt][2] = NEG_HUGE;
            if ((wh >> (bit + 1)) & 1) s[nt][3] = NEG_HUGE;
        }
        // online softmax (rows g: lo / g+8: hi; reduce across tig via shfl 1,2)
        float tm_lo = -INFINITY, tm_hi = -INFINITY;
#pragma unroll
        for (int nt = 0; nt < 8; nt++) {
            tm_lo = fmaxf(tm_lo, fmaxf(s[nt][0], s[nt][1]));
            tm_hi = fmaxf(tm_hi, fmaxf(s[nt][2], s[nt][3]));
        }
        tm_lo = fmaxf(tm_lo, __shfl_xor_sync(0xffffffffu, tm_lo, 1));
        tm_lo = fmaxf(tm_lo, __shfl_xor_sync(0xffffffffu, tm_lo, 2));
        tm_hi = fmaxf(tm_hi, __shfl_xor_sync(0xffffffffu, tm_hi, 1));
        tm_hi = fmaxf(tm_hi, __shfl_xor_sync(0xffffffffu, tm_hi, 2));
        float mn_lo = fmaxf(m_lo, tm_lo), mn_hi = fmaxf(m_hi, tm_hi);
        float sc_lo = __expf(m_lo - mn_lo), sc_hi = __expf(m_hi - mn_hi);
        m_lo = mn_lo; m_hi = mn_hi;
        float rs_lo = 0.f, rs_hi = 0.f;
        unsigned ph[8][2];
#pragma unroll
        for (int nt = 0; nt < 8; nt++) {
            float p0 = __expf(s[nt][0] - m_lo);
            float p1 = __expf(s[nt][1] - m_lo);
            float p2 = __expf(s[nt][2] - m_hi);
            float p3 = __expf(s[nt][3] - m_hi);
            rs_lo += p0 + p1; rs_hi += p2 + p3;
            ph[nt][0] = h2u(__floats2half2_rn(p0, p1));   // row g
            ph[nt][1] = h2u(__floats2half2_rn(p2, p3));   // row g+8
            o[nt][0] *= sc_lo; o[nt][1] *= sc_lo; o[nt][2] *= sc_hi; o[nt][3] *= sc_hi;
        }
        rs_lo += __shfl_xor_sync(0xffffffffu, rs_lo, 1);
        rs_lo += __shfl_xor_sync(0xffffffffu, rs_lo, 2);
        rs_hi += __shfl_xor_sync(0xffffffffu, rs_hi, 1);
        rs_hi += __shfl_xor_sync(0xffffffffu, rs_hi, 2);
        l_lo = l_lo * sc_lo + rs_lo;
        l_hi = l_hi * sc_hi + rs_hi;
        // O += P V  (P from registers; B from transposed V)
#pragma unroll
        for (int ks = 0; ks < 4; ks++) {
            unsigned pa[4];
            pa[0] = ph[2*ks][0];   // row g,   keys ks*16+2tig..+1
            pa[1] = ph[2*ks][1];   // row g+8
            pa[2] = ph[2*ks+1][0]; // row g,   keys ks*16+8+2tig..+1
            pa[3] = ph[2*ks+1][1]; // row g+8
#pragma unroll
            for (int nt = 0; nt < 8; nt++) {
                unsigned b0 = *(unsigned*)&VT[(nt*8+g)*AT_STR + ks*16 + 2*tig];
                unsigned b1 = *(unsigned*)&VT[(nt*8+g)*AT_STR + ks*16 + 8 + 2*tig];
                mma_f16(o[nt], pa, b0, b1);
            }
        }
    }
    float il = 1.f / l_lo, ih = 1.f / l_hi;
    size_t obase_lo = qlo_row * DD + h * 64;
    size_t obase_hi = qhi_row * DD + h * 64;
#pragma unroll
    for (int nt = 0; nt < 8; nt++) {
        int c = nt*8 + 2*tig;
        *(float2*)(g_CTX + obase_lo + c) = make_float2(o[nt][0]*il, o[nt][1]*il);
        *(float2*)(g_CTX + obase_hi + c) = make_float2(o[nt][2]*ih, o[nt][3]*ih);
    }
}

// ---------------- launch ----------------
extern "C" void kernel_launch(void* const* d_in, const int* in_sizes, int n_in,
                              void* d_out, int out_size) {
    const float* queries = (const float*)d_in[0];
    const float* keys    = (const float*)d_in[1];
    const float* values  = (const float*)d_in[2];
    const float* ln_q_g  = (const float*)d_in[3];
    const float* ln_q_b  = (const float*)d_in[4];
    const float* ln_k_g  = (const float*)d_in[5];
    const float* ln_k_b  = (const float*)d_in[6];
    const float* ln_v_g  = (const float*)d_in[7];
    const float* ln_v_b  = (const float*)d_in[8];
    const float* Wq = (const float*)d_in[9];   const float* bq = (const float*)d_in[10];
    const float* Wk = (const float*)d_in[11];  const float* bk = (const float*)d_in[12];
    const float* Wv = (const float*)d_in[13];  const float* bv = (const float*)d_in[14];
    const float* Wo = (const float*)d_in[15];  const float* bo = (const float*)d_in[16];
    const float* Ww1 = (const float*)d_in[17]; const float* bw1 = (const float*)d_in[18];
    const float* Ww2 = (const float*)d_in[19]; const float* bw2 = (const float*)d_in[20];
    float* out = (float*)d_out;

    float *QN, *KN, *VN, *Qh, *Kh, *Vh, *CTX, *HID;
    cudaGetSymbolAddress((void**)&QN, g_QN);
    cudaGetSymbolAddress((void**)&KN, g_KN);
    cudaGetSymbolAddress((void**)&VN, g_VN);
    cudaGetSymbolAddress((void**)&Qh, g_Qh);
    cudaGetSymbolAddress((void**)&Kh, g_Kh);
    cudaGetSymbolAddress((void**)&Vh, g_Vh);
    cudaGetSymbolAddress((void**)&CTX, g_CTX);
    cudaGetSymbolAddress((void**)&HID, g_HID);

    init_kernel<<<1, 128>>>();
    ln_warp_kernel<<<NROWS/8, 256>>>(queries, ln_q_g, ln_q_b, QN, 1);
    ln_warp_kernel<<<NROWS/8, 256>>>(keys,    ln_k_g, ln_k_b, KN, 0);
    ln_warp_kernel<<<NROWS/8, 256>>>(values,  ln_v_g, ln_v_b, VN, 0);

    // window MLP hidden (fp32 — rintf-sensitive path)
    gemm_kernel<<<dim3(2, 64), 256>>>(QN, Ww1, bw1, nullptr, HID, 128, 1);
    winred_kernel<<<NROWS, 128>>>(Ww2, bw2);

    dm_kernel<<<NROWS, 256>>>();
    batchstat_kernel<<<BB, 1024>>>();
    kp_kernel<<<BB, 1024>>>();
    gumbel_kernel<<<BB * 4, 512>>>();
    maskbuild_kernel<<<NROWS, 64>>>();
    needed_kernel<<<1, 32>>>();
    fill_kernel<<<(BB * NRAND) / 256, 256>>>();

    // projections (fp16 MMA)
    gemm_h_kernel<<<dim3(8, 64), 128>>>(QN, Wq, bq, nullptr, Qh, 512);
    gemm_h_kernel<<<dim3(8, 64), 128>>>(KN, Wk, bk, nullptr, Kh, 512);
    gemm_h_kernel<<<dim3(8, 64), 128>>>(VN, Wv, bv, nullptr, Vh, 512);

    // attention (fp16 MMA flash)
    attn_h_kernel<<<dim3(SS / 64, BB * HH), 128>>>();

    // output projection + residual (fp16 MMA)
    gemm_h_kernel<<<dim3(8, 64), 128>>>(CTX, Wo, bo, queries, out, 512);
}

// round 8
// speedup vs baseline: 3.8930x; 1.5826x over previous
#include <cuda_runtime.h>
#include <cuda_bf16.h>
#include <cuda_fp16.h>
#include <math.h>
#include <stdint.h>

// ---------------- problem constants ----------------
#define BB 2
#define SS 2048
#define DD 512
#define HH 8
#define NROWS (BB*SS)            // 4096
#define MWORDS (SS/32)           // 64
#define NRAND (SS*SS/2)          // 2097152 (power of two)
#define NEG_HUGE (-3.4028234663852886e38f)
#define TINYF 1.17549435e-38f

#define TF_PARTITIONABLE 1

// ---------------- scratch (device globals; no runtime alloc) ----------------
__device__ float  g_QN[NROWS*DD];          // fp32 qn (mask path)
__device__ __half g_QNh[NROWS*DD];
__device__ __half g_KNh[NROWS*DD];
__device__ __half g_VNh[NROWS*DD];
__device__ __half g_Wqh[DD*DD], g_Wkh[DD*DD], g_Wvh[DD*DD], g_Woh[DD*DD];
__device__ __half g_Qhh[NROWS*DD];         // Q proj, pre-scaled 1/8
__device__ __half g_Khh[NROWS*DD];
__device__ __half g_Vhh[NROWS*DD];
__device__ __half g_VTh[NROWS*DD];         // [(b*8+h)*64 + d]*2048 + s
__device__ __half g_CTXh[NROWS*DD];
__device__ float  g_HID[NROWS*128];
__device__ unsigned g_MASK[NROWS*MWORDS];
__device__ float g_DM[NROWS], g_CH[NROWS], g_MAG[NROWS], g_VAR1[NROWS], g_IMP[NROWS];
__device__ int   g_WIN[NROWS];
__device__ unsigned char g_KPB[NROWS];
__device__ unsigned g_KPW[BB*MWORDS];
__device__ unsigned g_CSW[BB*MWORDS];
__device__ float g_THR[BB], g_COMP[BB], g_IMPLO[BB], g_IMPHI[BB];
__device__ int   g_HASKP[BB], g_COUNT[BB], g_NEEDED[BB];
__device__ unsigned g_KEY_G[2], g_KEY_Q[2], g_KEY_K[2];

// ---------------- threefry-2x32 (JAX 20-round) ----------------
__device__ __forceinline__ void tf2x32(unsigned k0, unsigned k1, unsigned x0, unsigned x1,
                                       unsigned &o0, unsigned &o1) {
    unsigned ks2 = k0 ^ k1 ^ 0x1BD11BDAu;
    x0 += k0; x1 += k1;
#define TFR(r) { x0 += x1; x1 = (x1 << r) | (x1 >> (32 - r)); x1 ^= x0; }
    TFR(13) TFR(15) TFR(26) TFR(6)
    x0 += k1;  x1 += ks2 + 1u;
    TFR(17) TFR(29) TFR(16) TFR(24)
    x0 += ks2; x1 += k0 + 2u;
    TFR(13) TFR(15) TFR(26) TFR(6)
    x0 += k0;  x1 += k1 + 3u;
    TFR(17) TFR(29) TFR(16) TFR(24)
    x0 += k1;  x1 += ks2 + 4u;
    TFR(13) TFR(15) TFR(26) TFR(6)
    x0 += ks2; x1 += k0 + 5u;
#undef TFR
    o0 = x0; o1 = x1;
}

__device__ __forceinline__ unsigned tf_bits(unsigned k0, unsigned k1,
                                            unsigned long long idx,
                                            unsigned long long total) {
#if TF_PARTITIONABLE
    unsigned o0, o1;
    tf2x32(k0, k1, (unsigned)(idx >> 32), (unsigned)idx, o0, o1);
    return o0 ^ o1;
#else
    unsigned long long half = (total + 1ull) / 2ull;
    unsigned o0, o1;
    if (idx < half) { tf2x32(k0, k1, (unsigned)idx, (unsigned)(idx + half), o0, o1); return o0; }
    else            { tf2x32(k0, k1, (unsigned)(idx - half), (unsigned)idx, o0, o1); return o1; }
#endif
}

// ---------------- fp16 MMA helper ----------------
__device__ __forceinline__ void mma_f16(float d[4], const unsigned a[4],
                                        unsigned b0, unsigned b1) {
    asm volatile("mma.sync.aligned.m16n8k16.row.col.f32.f16.f16.f32 "
        "{%0,%1,%2,%3}, {%4,%5,%6,%7}, {%8,%9}, {%0,%1,%2,%3};"
        : "+f"(d[0]), "+f"(d[1]), "+f"(d[2]), "+f"(d[3])
        : "r"(a[0]), "r"(a[1]), "r"(a[2]), "r"(a[3]), "r"(b0), "r"(b1));
}
__device__ __forceinline__ unsigned h2u(__half2 h) { return *(unsigned*)&h; }

// ---------------- block reductions ----------------
__device__ __forceinline__ float bredSum(float v, float* s, int n) {
    int t = threadIdx.x; s[t] = v; __syncthreads();
    for (int k = n >> 1; k > 0; k >>= 1) { if (t < k) s[t] += s[t + k]; __syncthreads(); }
    float r = s[0]; __syncthreads(); return r;
}
__device__ __forceinline__ float bredMax(float v, float* s, int n) {
    int t = threadIdx.x; s[t] = v; __syncthreads();
    for (int k = n >> 1; k > 0; k >>= 1) { if (t < k) s[t] = fmaxf(s[t], s[t + k]); __syncthreads(); }
    float r = s[0]; __syncthreads(); return r;
}
__device__ __forceinline__ float bredMin(float v, float* s, int n) {
    int t = threadIdx.x; s[t] = v; __syncthreads();
    for (int k = n >> 1; k > 0; k >>= 1) { if (t < k) s[t] = fminf(s[t], s[t + k]); __syncthreads(); }
    float r = s[0]; __syncthreads(); return r;
}

// ---------------- init ----------------
__global__ void init_kernel() {
    int t = blockIdx.x * blockDim.x + threadIdx.x;
    if (t < BB*MWORDS) g_CSW[t] = 0u;
    if (t < BB) g_COUNT[t] = 0;
    if (t == 0) {
        unsigned o0, o1, a0, a1;
        tf2x32(0u, 42u, 0u, 0u, o0, o1); g_KEY_G[0] = o0; g_KEY_G[1] = o1;
#if TF_PARTITIONABLE
        tf2x32(0u, 42u, 0u, 1u, o0, o1);
        tf2x32(o0, o1, 0u, 1u, a0, a1); g_KEY_Q[0] = a0; g_KEY_Q[1] = a1;
        tf2x32(0u, 42u, 0u, 2u, o0, o1);
        tf2x32(o0, o1, 0u, 1u, a0, a1); g_KEY_K[0] = a0; g_KEY_K[1] = a1;
#else
        unsigned p0, p1, q0, q1;
        tf2x32(0u, 42u, 0u, 1u, o0, o1);
        tf2x32(o0, o1, 0u, 2u, p0, p1);
        tf2x32(o0, o1, 1u, 3u, q0, q1);
        g_KEY_Q[0] = p1; g_KEY_Q[1] = q1;
        tf2x32(0u, 42u, 0u, 2u, o0, o1);
        tf2x32(o0, o1, 0u, 2u, p0, p1);
        tf2x32(o0, o1, 1u, 3u, q0, q1);
        g_KEY_K[0] = p1; g_KEY_K[1] = q1;
#endif
    }
}

// ---------------- warp-per-row LayerNorm -> fp32 and/or half (+qn stats) ------
__global__ void ln_warp_kernel(const float* __restrict__ x, const float* __restrict__ gam,
                               const float* __restrict__ bet, float* __restrict__ yf,
                               __half* __restrict__ yh, int stats) {
    int w = threadIdx.x >> 5, lane = threadIdx.x & 31;
    int row = blockIdx.x * 8 + w;
    const float4* xr = (const float4*)(x + (size_t)row * 512);
    float4 v[4];
#pragma unroll
    for (int j = 0; j < 4; j++) v[j] = xr[lane + j * 32];
    float s = 0.f;
#pragma unroll
    for (int j = 0; j < 4; j++) s += v[j].x + v[j].y + v[j].z + v[j].w;
#pragma unroll
    for (int o = 16; o > 0; o >>= 1) s += __shfl_xor_sync(0xffffffffu, s, o);
    float mu = s * (1.f / 512.f);
    float qv = 0.f;
#pragma unroll
    for (int j = 0; j < 4; j++) {
        float a = v[j].x - mu, b = v[j].y - mu, c = v[j].z - mu, d = v[j].w - mu;
        qv += a * a + b * b + c * c + d * d;
    }
#pragma unroll
    for (int o = 16; o > 0; o >>= 1) qv += __shfl_xor_sync(0xffffffffu, qv, o);
    float r = rsqrtf(qv * (1.f / 512.f) + 1e-5f);
    const float4* g4 = (const float4*)gam;
    const float4* b4 = (const float4*)bet;
    float yv[16];
#pragma unroll
    for (int j = 0; j < 4; j++) {
        float4 gg = g4[lane + j * 32], bb = b4[lane + j * 32];
        float4 o4;
        o4.x = (v[j].x - mu) * r * gg.x + bb.x;
        o4.y = (v[j].y - mu) * r * gg.y + bb.y;
        o4.z = (v[j].z - mu) * r * gg.z + bb.z;
        o4.w = (v[j].w - mu) * r * gg.w + bb.w;
        if (yf) ((float4*)(yf + (size_t)row * 512))[lane + j * 32] = o4;
        if (yh) {
            __half2 h01 = __floats2half2_rn(o4.x, o4.y);
            __half2 h23 = __floats2half2_rn(o4.z, o4.w);
            *(uint2*)(yh + (size_t)row * 512 + (lane + j * 32) * 4) =
                make_uint2(h2u(h01), h2u(h23));
        }
        yv[j*4+0] = o4.x; yv[j*4+1] = o4.y; yv[j*4+2] = o4.z; yv[j*4+3] = o4.w;
    }
    if (stats) {
        float sq = 0.f, sy = 0.f;
#pragma unroll
        for (int i = 0; i < 16; i++) { sq += yv[i] * yv[i]; sy += yv[i]; }
#pragma unroll
        for (int o = 16; o > 0; o >>= 1) {
            sq += __shfl_xor_sync(0xffffffffu, sq, o);
            sy += __shfl_xor_sync(0xffffffffu, sy, o);
        }
        float my = sy * (1.f / 512.f);
        float sd = 0.f;
#pragma unroll
        for (int i = 0; i < 16; i++) { float e = yv[i] - my; sd += e * e; }
#pragma unroll
        for (int o = 16; o > 0; o >>= 1) sd += __shfl_xor_sync(0xffffffffu, sd, o);
        if (lane == 0) { g_MAG[row] = sqrtf(sq); g_VAR1[row] = sd * (1.f / 511.f); }
    }
}

// ---------------- weight fp32 -> half ----------------
__global__ void wconv_kernel(const float* __restrict__ W, __half* __restrict__ Wh) {
    int i = (blockIdx.x * blockDim.x + threadIdx.x) * 4;   // over 262144 elems
    float4 v = *(const float4*)(W + i);
    __half2 h01 = __floats2half2_rn(v.x, v.y);
    __half2 h23 = __floats2half2_rn(v.z, v.w);
    *(uint2*)(Wh + i) = make_uint2(h2u(h01), h2u(h23));
}

// ---------------- fp32 GEMM (window-MLP hidden only; rintf-sensitive) ---------
__global__ void gemm_kernel(const float* __restrict__ A, const float* __restrict__ W,
                            const float* __restrict__ bias, float* __restrict__ C,
                            int N, int doRelu) {
    __shared__ float As[64][17];
    __shared__ float Ws[64][17];
    int row0 = blockIdx.y * 64;
    int col0 = blockIdx.x * 64;
    int tid = threadIdx.x;
    int tx = tid & 15, ty = tid >> 4;
    int r0 = ty * 4, c0 = tx * 4;
    int lr = tid >> 2, lc4 = (tid & 3) * 4;
    float acc[4][4] = {};
    for (int kk = 0; kk < 512; kk += 16) {
        float4 av = *reinterpret_cast<const float4*>(A + (size_t)(row0 + lr) * 512 + kk + lc4);
        float4 wv = *reinterpret_cast<const float4*>(W + (size_t)(col0 + lr) * 512 + kk + lc4);
        As[lr][lc4] = av.x; As[lr][lc4+1] = av.y; As[lr][lc4+2] = av.z; As[lr][lc4+3] = av.w;
        Ws[lr][lc4] = wv.x; Ws[lr][lc4+1] = wv.y; Ws[lr][lc4+2] = wv.z; Ws[lr][lc4+3] = wv.w;
        __syncthreads();
#pragma unroll
        for (int kc = 0; kc < 16; kc++) {
            float a0 = As[r0][kc], a1 = As[r0+1][kc], a2 = As[r0+2][kc], a3 = As[r0+3][kc];
            float b0 = Ws[c0][kc], b1 = Ws[c0+1][kc], b2 = Ws[c0+2][kc], b3 = Ws[c0+3][kc];
            acc[0][0] += a0*b0; acc[0][1] += a0*b1; acc[0][2] += a0*b2; acc[0][3] += a0*b3;
            acc[1][0] += a1*b0; acc[1][1] += a1*b1; acc[1][2] += a1*b2; acc[1][3] += a1*b3;
            acc[2][0] += a2*b0; acc[2][1] += a2*b1; acc[2][2] += a2*b2; acc[2][3] += a2*b3;
            acc[3][0] += a3*b0; acc[3][1] += a3*b1; acc[3][2] += a3*b2; acc[3][3] += a3*b3;
        }
        __syncthreads();
    }
#pragma unroll
    for (int i = 0; i < 4; i++) {
#pragma unroll
        for (int j = 0; j < 4; j++) {
            int col = col0 + c0 + j;
            size_t ro = (size_t)(row0 + r0 + i);
            float v = acc[i][j] + bias[col];
            if (doRelu) v = fmaxf(v, 0.f);
            C[ro * (size_t)N + col] = v;
        }
    }
}

// ---------------- fp16 MMA GEMM: A[4096][512](h) @ W[512][512]^T(h) + b --------
// Output: half*oscale (Ch) OR float + resid (Cf).
#define GS 40
__global__ void __launch_bounds__(128) gemm_h_kernel(
        const __half* __restrict__ A, const __half* __restrict__ W,
        const float* __restrict__ bias, const float* __restrict__ resid,
        float* __restrict__ Cf, __half* __restrict__ Ch, float oscale) {
    __shared__ __half As[64*GS];
    __shared__ __half Ws[64*GS];
    int tid = threadIdx.x;
    int w = tid >> 5, lane = tid & 31, g = lane >> 2, tig = lane & 3;
    int col0 = blockIdx.x * 64, row0 = blockIdx.y * 64;
    int wq = w * 16;
    float acc[8][4];
#pragma unroll
    for (int nt = 0; nt < 8; nt++) { acc[nt][0]=0; acc[nt][1]=0; acc[nt][2]=0; acc[nt][3]=0; }
    for (int kc = 0; kc < 512; kc += 32) {
#pragma unroll
        for (int it = 0; it < 2; it++) {
            int idx = tid + it * 128;                 // 256 uint4 per array
            int r = idx >> 2, c8 = (idx & 3) * 8;
            *(uint4*)&As[r*GS + c8] = *(const uint4*)&A[(size_t)(row0 + r) * 512 + kc + c8];
            *(uint4*)&Ws[r*GS + c8] = *(const uint4*)&W[(size_t)(col0 + r) * 512 + kc + c8];
        }
        __syncthreads();
#pragma unroll
        for (int ks = 0; ks < 2; ks++) {
            unsigned a[4];
            a[0] = *(unsigned*)&As[(wq+g)*GS   + ks*16 + 2*tig];
            a[1] = *(unsigned*)&As[(wq+g+8)*GS + ks*16 + 2*tig];
            a[2] = *(unsigned*)&As[(wq+g)*GS   + ks*16 + 8 + 2*tig];
            a[3] = *(unsigned*)&As[(wq+g+8)*GS + ks*16 + 8 + 2*tig];
#pragma unroll
            for (int nt = 0; nt < 8; nt++) {
                unsigned b0 = *(unsigned*)&Ws[(nt*8+g)*GS + ks*16 + 2*tig];
                unsigned b1 = *(unsigned*)&Ws[(nt*8+g)*GS + ks*16 + 8 + 2*tig];
                mma_f16(acc[nt], a, b0, b1);
            }
        }
        __syncthreads();
    }
    int rlo = row0 + wq + g, rhi = rlo + 8;
#pragma unroll
    for (int nt = 0; nt < 8; nt++) {
        int c = col0 + nt*8 + 2*tig;
        float v0 = acc[nt][0] + bias[c],   v1 = acc[nt][1] + bias[c+1];
        float v2 = acc[nt][2] + bias[c],   v3 = acc[nt][3] + bias[c+1];
        if (Ch) {
            __half2 lo = __floats2half2_rn(v0 * oscale, v1 * oscale);
            __half2 hi = __floats2half2_rn(v2 * oscale, v3 * oscale);
            *(unsigned*)&Ch[(size_t)rlo * 512 + c] = h2u(lo);
            *(unsigned*)&Ch[(size_t)rhi * 512 + c] = h2u(hi);
        } else {
            v0 += resid[(size_t)rlo * 512 + c];   v1 += resid[(size_t)rlo * 512 + c + 1];
            v2 += resid[(size_t)rhi * 512 + c];   v3 += resid[(size_t)rhi * 512 + c + 1];
            Cf[(size_t)rlo * 512 + c] = v0; Cf[(size_t)rlo * 512 + c + 1] = v1;
            Cf[(size_t)rhi * 512 + c] = v2; Cf[(size_t)rhi * 512 + c + 1] = v3;
        }
    }
}

// ---------------- V transpose: g_Vhh[row][col] -> g_VTh[(b*8+h)*64+d][s] -------
__global__ void vtrans_kernel() {
    __shared__ __half t[32][33];
    int r0 = blockIdx.x * 32;     // global row (b*2048+s), grid.x = 128
    int c0 = blockIdx.y * 32;     // column (h*64+d), grid.y = 16
    int tx = threadIdx.x & 31, ty = threadIdx.x >> 5;   // 256 threads: ty 0..7
#pragma unroll
    for (int i = 0; i < 4; i++)
        t[ty + 8*i][tx] = g_Vhh[(size_t)(r0 + ty + 8*i) * 512 + c0 + tx];
    __syncthreads();
    int b = r0 >> 11;
    int h = c0 >> 6, d0 = c0 & 63;
#pragma unroll
    for (int i = 0; i < 4; i++) {
        int d = d0 + ty + 8*i;
        g_VTh[((size_t)(b * 8 + h) * 64 + d) * 2048 + (r0 & 2047) + tx] = t[tx][ty + 8*i];
    }
}

// ---------------- window reduce ----------------
__global__ void winred_kernel(const float* __restrict__ W2, const float* __restrict__ b2) {
    __shared__ float sb[128];
    int row = blockIdx.x, tid = threadIdx.x;
    sb[tid] = g_HID[(size_t)row * 128 + tid] * W2[tid];
    __syncthreads();
    for (int st = 64; st > 0; st >>= 1) { if (tid < st) sb[tid] += sb[tid + st]; __syncthreads(); }
    if (tid == 0) {
        float s = sb[0] + b2[0];
        float adj = 0.5f + 1.0f / (1.0f + expf(-s));
        int w = (int)rintf(64.0f * adj);
        g_WIN[row] = min(max(w, 1), 128);
    }
}

// ---------------- dm/ch/imp ----------------
__global__ void dm_kernel() {
    __shared__ float sb[256];
    int row = blockIdx.x, tid = threadIdx.x;
    int t = row & (SS - 1);
    const float* q0 = g_QN + (size_t)row * DD;
    float acc = 0.f, chs = 0.f;
    const int   sv[4] = {1, 2, 3, 5};
    const float wv[4] = {0.4f, 0.3f, 0.2f, 0.1f};
    for (int l = 0; l < 2; l++) {
        int d = tid + l * 256;
        float base = q0[d];
#pragma unroll
        for (int si = 0; si < 4; si++) {
            int s = sv[si];
            if (t + s < SS)
                acc += wv[si] * (fabsf(q0[(size_t)s * DD + d] - base) / (float)s);
        }
        if (t < SS - 1) chs += fabsf(q0[DD + d] - base);
    }
    float a = bredSum(acc, sb, 256);
    float c = bredSum(chs, sb, 256);
    if (tid == 0) {
        float chv = c * (1.f / 512.f);
        g_DM[row] = a * (1.f / 512.f);
        g_CH[row] = chv;
        g_IMP[row] = 0.5f * g_MAG[row] + 0.5f * chv;
    }
}

// ---------------- per-batch stats ----------------
__global__ void batchstat_kernel() {
    __shared__ float sb[1024];
    int b = blockIdx.x, tid = threadIdx.x;
    int r0 = b * SS + tid, r1 = r0 + 1024;
    float d0 = g_DM[r0], d1 = g_DM[r1];
    float mean = bredSum(d0 + d1, sb, 1024) * (1.f / 2048.f);
    float e0 = d0 - mean, e1 = d1 - mean;
    float var = bredSum(e0 * e0 + e1 * e1, sb, 1024) * (1.f / 2047.f);
    float comp = bredSum(g_VAR1[r0] + g_VAR1[r1], sb, 1024) * (1.f / 2048.f);
    float i0 = g_IMP[r0], i1 = g_IMP[r1];
    float lo = bredMin(fminf(i0, i1), sb, 1024);
    float hi = bredMax(fmaxf(i0, i1), sb, 1024);
    if (tid == 0) {
        g_THR[b] = mean + 0.5f * sqrtf(var);
        g_COMP[b] = comp;
        g_IMPLO[b] = lo; g_IMPHI[b] = hi;
    }
}

// ---------------- keypoints ----------------
__global__ void kp_kernel() {
    __shared__ unsigned char kpf[SS];
    __shared__ int anyf;
    int b = blockIdx.x, tid = threadIdx.x;
    if (tid == 0) anyf = 0;
    __syncthreads();
    float thr = g_THR[b];
    for (int it = 0; it < 2; it++) {
        int t = tid + it * 1024;
        int row = b * SS + t;
        float dm = g_DM[row];
        float left  = (t > 0)      ? g_DM[row - 1] : -1.0f;
        float right = (t < SS - 1) ? g_DM[row + 1] : -1.0f;
        int kp = (dm > thr) && (dm > left) && (dm > right);
        if (t == 0 || t == SS - 1) kp = kp || (dm > thr);
        kpf[t] = (unsigned char)kp;
        g_KPB[row] = (unsigned char)kp;
        if (kp) anyf = 1;
    }
    __syncthreads();
    if (tid < MWORDS) {
        unsigned w = 0;
        for (int j = 0; j < 32; j++) if (kpf[tid * 32 + j]) w |= (1u << j);
        g_KPW[b * MWORDS + tid] = w;
    }
    if (tid == 0) g_HASKP[b] = anyf;
}

// ---------------- stratified gumbel top-4 ----------------
__global__ void gumbel_kernel() {
    __shared__ float sb[512];
    __shared__ float lv[512];
    __shared__ int si[512];
    int seg = blockIdx.x;
    int b = seg >> 2, l = seg & 3;
    int tid = threadIdx.x;
    int t = l * 512 + tid;
    int row = b * SS + t;
    float lo = g_IMPLO[b], hi = g_IMPHI[b];
    float ip = (g_IMP[row] - lo) / (hi - lo + 1e-6f);
    float ssum = bredSum(ip, sb, 512);
    float prob = ip / (ssum + 1e-6f);
    unsigned bits = tf_bits(g_KEY_G[0], g_KEY_G[1], (unsigned long long)(seg * 512 + tid), 4096ull);
    float f = __uint_as_float((bits >> 9) | 0x3f800000u) - 1.0f;
    float u = fmaxf(TINYF, f * (1.0f - TINYF) + TINYF);
    float gum = -logf(-logf(u));
    lv[tid] = logf(prob + 1e-20f) + gum;
    __syncthreads();
    for (int round = 0; round < 4; round++) {
        sb[tid] = lv[tid]; si[tid] = tid;
        __syncthreads();
        for (int st = 256; st > 0; st >>= 1) {
            if (tid < st) {
                float ov = sb[tid + st]; int oi = si[tid + st];
                if (ov > sb[tid] || (ov == sb[tid] && oi < si[tid])) { sb[tid] = ov; si[tid] = oi; }
            }
            __syncthreads();
        }
        if (tid == 0) {
            int sel = si[0];
            int tt = l * 512 + sel;
            atomicOr(&g_CSW[b * MWORDS + (tt >> 5)], 1u << (tt & 31));
            lv[sel] = -INFINITY;
        }
        __syncthreads();
    }
}

// ---------------- mask build + density ----------------
__device__ __forceinline__ unsigned range_word(int lo, int hi, int kb) {
    int a = lo - kb, e = hi - kb;
    if (e < 0 || a > 31) return 0u;
    a = max(a, 0); e = min(e, 31);
    unsigned m = (e == 31) ? 0xFFFFFFFFu : ((1u << (e + 1)) - 1u);
    return m & (0xFFFFFFFFu << a);
}

__global__ void maskbuild_kernel() {
    int row = blockIdx.x;
    int b = row >> 11, q = row & (SS - 1);
    int w = threadIdx.x;
    int kb = w * 32;
    int win = g_WIN[row];
    unsigned m = range_word(max(q - win, 0), min(q + win, SS - 1), kb);
    if (g_HASKP[b]) {
        m |= g_KPB[row] ? 0xFFFFFFFFu : g_KPW[b * MWORDS + w];
    } else {
        unsigned fbw = ((w == 0) ? 1u : 0u) | (((w & 15) == 15) ? 0x80000000u : 0u);
        int qin = (q == 0 || q == 511 || q == 1023 || q == 1535 || q == 2047);
        m |= qin ? 0xFFFFFFFFu : fbw;
    }
    m |= g_CSW[b * MWORDS + w];
    g_MASK[(size_t)row * MWORDS + w] = m;
    int pc = __popc(m);
#pragma unroll
    for (int o = 16; o > 0; o >>= 1) pc += __shfl_down_sync(0xffffffffu, pc, o);
    __shared__ int ws[2];
    if ((w & 31) == 0) ws[w >> 5] = pc;
    __syncthreads();
    if (w == 0) atomicAdd(&g_COUNT[b], ws[0] + ws[1]);
}

// ---------------- needed ----------------
__global__ void needed_kernel() {
    if (threadIdx.x == 0) {
        float c0 = g_COMP[0], c1 = g_COMP[1];
        float mn = fminf(c0, c1), mx = fmaxf(c0, c1);
        for (int b = 0; b < BB; b++) {
            float nc = (g_COMP[b] - mn) / (mx - mn + 1e-6f);
            float ratio = fminf(fmaxf(0.3f * (0.5f + nc), 0.1f), 0.5f);
            float dens = (float)g_COUNT[b] / 4194304.0f;
            float nd = ceilf((ratio - dens) * 4194304.0f);
            int n = (int)nd;
            g_NEEDED[b] = max(n, 0);
        }
    }
}

// ---------------- random fill ----------------
__global__ void fill_kernel() {
    unsigned long long j = (unsigned long long)blockIdx.x * blockDim.x + threadIdx.x;
    if (j >= (unsigned long long)BB * NRAND) return;
    int b = (int)(j >> 21);
    int i = (int)(j & (NRAND - 1));
    if (i < g_NEEDED[b]) {
        unsigned qb = tf_bits(g_KEY_Q[0], g_KEY_Q[1], j, (unsigned long long)BB * NRAND);
        unsigned kb = tf_bits(g_KEY_K[0], g_KEY_K[1], j, (unsigned long long)BB * NRAND);
        int qr = qb & (SS - 1), kr = kb & (SS - 1);
        atomicOr(&g_MASK[((size_t)(b * SS + qr)) * MWORDS + (kr >> 5)], 1u << (kr & 31));
    }
}

// ---------------- flash attention, fp16 MMA, q-tile 128, 8 warps ----------------
#define AT_STR 72
__global__ void __launch_bounds__(256) attn_h2_kernel() {
    __shared__ __half Ks[64*AT_STR];
    __shared__ __half VT[64*AT_STR];
    int tid = threadIdx.x;
    int w = tid >> 5, lane = tid & 31;
    int g = lane >> 2, tig = lane & 3;
    int qt = blockIdx.x, bh = blockIdx.y;
    int b = bh >> 3, h = bh & 7;
    int q0 = qt * 128, wq = w * 16;
    size_t qlo_row = (size_t)(b * SS + q0 + wq + g);
    size_t qhi_row = qlo_row + 8;

    // Q fragments direct from global (half, pre-scaled 1/8)
    const __half* Qlo = g_Qhh + qlo_row * 512 + h * 64;
    const __half* Qhi = g_Qhh + qhi_row * 512 + h * 64;
    unsigned qa[4][4];
#pragma unroll
    for (int ks = 0; ks < 4; ks++) {
        qa[ks][0] = *(const unsigned*)(Qlo + ks*16 + 2*tig);
        qa[ks][1] = *(const unsigned*)(Qhi + ks*16 + 2*tig);
        qa[ks][2] = *(const unsigned*)(Qlo + ks*16 + 8 + 2*tig);
        qa[ks][3] = *(const unsigned*)(Qhi + ks*16 + 8 + 2*tig);
    }
    float o[8][4];
#pragma unroll
    for (int nt = 0; nt < 8; nt++) { o[nt][0]=0; o[nt][1]=0; o[nt][2]=0; o[nt][3]=0; }
    float m_lo = -INFINITY, m_hi = -INFINITY, l_lo = 0.f, l_hi = 0.f;
    const unsigned* mrow_lo = g_MASK + qlo_row * MWORDS;
    const unsigned* mrow_hi = g_MASK + qhi_row * MWORDS;
    const __half* Kbase  = g_Khh + ((size_t)(b * SS)) * 512 + h * 64;
    const __half* VTbase = g_VTh + ((size_t)bh * 64) * 2048;

    for (int k0 = 0; k0 < SS; k0 += 64) {
        __syncthreads();
#pragma unroll
        for (int it = 0; it < 2; it++) {
            int idx = tid + it * 256;                 // 512 uint4 per array
            int r = idx >> 3, c8 = (idx & 7) * 8;
            *(uint4*)&Ks[r*AT_STR + c8] = *(const uint4*)(Kbase + (size_t)(k0 + r) * 512 + c8);
            *(uint4*)&VT[r*AT_STR + c8] = *(const uint4*)(VTbase + (size_t)r * 2048 + k0 + c8);
        }
        __syncthreads();
        // S = (Q/8) K^T
        float s[8][4];
#pragma unroll
        for (int nt = 0; nt < 8; nt++) { s[nt][0]=0; s[nt][1]=0; s[nt][2]=0; s[nt][3]=0; }
#pragma unroll
        for (int ks = 0; ks < 4; ks++) {
#pragma unroll
            for (int nt = 0; nt < 8; nt++) {
                unsigned b0 = *(unsigned*)&Ks[(nt*8+g)*AT_STR + ks*16 + 2*tig];
                unsigned b1 = *(unsigned*)&Ks[(nt*8+g)*AT_STR + ks*16 + 8 + 2*tig];
                mma_f16(s[nt], qa[ks], b0, b1);
            }
        }
        // mask (bit set => masked OUT)
        unsigned ml0 = mrow_lo[k0 >> 5], ml1 = mrow_lo[(k0 >> 5) + 1];
        unsigned mh0 = mrow_hi[k0 >> 5], mh1 = mrow_hi[(k0 >> 5) + 1];
#pragma unroll
        for (int nt = 0; nt < 8; nt++) {
            int cb = nt*8 + 2*tig;
            unsigned wl = (cb < 32) ? ml0 : ml1;
            unsigned wh = (cb < 32) ? mh0 : mh1;
            int bit = cb & 31;
            if ((wl >> bit) & 1)       s[nt][0] = NEG_HUGE;
            if ((wl >> (bit + 1)) & 1) s[nt][1] = NEG_HUGE;
            if ((wh >> bit) & 1)       s[nt][2] = NEG_HUGE;
            if ((wh >> (bit + 1)) & 1) s[nt][3] = NEG_HUGE;
        }
        // online softmax
        float tm_lo = -INFINITY, tm_hi = -INFINITY;
#pragma unroll
        for (int nt = 0; nt < 8; nt++) {
            tm_lo = fmaxf(tm_lo, fmaxf(s[nt][0], s[nt][1]));
            tm_hi = fmaxf(tm_hi, fmaxf(s[nt][2], s[nt][3]));
        }
        tm_lo = fmaxf(tm_lo, __shfl_xor_sync(0xffffffffu, tm_lo, 1));
        tm_lo = fmaxf(tm_lo, __shfl_xor_sync(0xffffffffu, tm_lo, 2));
        tm_hi = fmaxf(tm_hi, __shfl_xor_sync(0xffffffffu, tm_hi, 1));
        tm_hi = fmaxf(tm_hi, __shfl_xor_sync(0xffffffffu, tm_hi, 2));
        float mn_lo = fmaxf(m_lo, tm_lo), mn_hi = fmaxf(m_hi, tm_hi);
        float sc_lo = __expf(m_lo - mn_lo), sc_hi = __expf(m_hi - mn_hi);
        m_lo = mn_lo; m_hi = mn_hi;
        float rs_lo = 0.f, rs_hi = 0.f;
        unsigned ph[8][2];
#pragma unroll
        for (int nt = 0; nt < 8; nt++) {
            float p0 = __expf(s[nt][0] - m_lo);
            float p1 = __expf(s[nt][1] - m_lo);
            float p2 = __expf(s[nt][2] - m_hi);
            float p3 = __expf(s[nt][3] - m_hi);
            rs_lo += p0 + p1; rs_hi += p2 + p3;
            ph[nt][0] = h2u(__floats2half2_rn(p0, p1));
            ph[nt][1] = h2u(__floats2half2_rn(p2, p3));
            o[nt][0] *= sc_lo; o[nt][1] *= sc_lo; o[nt][2] *= sc_hi; o[nt][3] *= sc_hi;
        }
        rs_lo += __shfl_xor_sync(0xffffffffu, rs_lo, 1);
        rs_lo += __shfl_xor_sync(0xffffffffu, rs_lo, 2);
        rs_hi += __shfl_xor_sync(0xffffffffu, rs_hi, 1);
        rs_hi += __shfl_xor_sync(0xffffffffu, rs_hi, 2);
        l_lo = l_lo * sc_lo + rs_lo;
        l_hi = l_hi * sc_hi + rs_hi;
        // O += P V
#pragma unroll
        for (int ks = 0; ks < 4; ks++) {
            unsigned pa[4];
            pa[0] = ph[2*ks][0];
            pa[1] = ph[2*ks][1];
            pa[2] = ph[2*ks+1][0];
            pa[3] = ph[2*ks+1][1];
#pragma unroll
            for (int nt = 0; nt < 8; nt++) {
                unsigned b0 = *(unsigned*)&VT[(nt*8+g)*AT_STR + ks*16 + 2*tig];
                unsigned b1 = *(unsigned*)&VT[(nt*8+g)*AT_STR + ks*16 + 8 + 2*tig];
                mma_f16(o[nt], pa, b0, b1);
            }
        }
    }
    float il = 1.f / l_lo, ih = 1.f / l_hi;
    __half* Clo = g_CTXh + qlo_row * 512 + h * 64;
    __half* Chi = g_CTXh + qhi_row * 512 + h * 64;
#pragma unroll
    for (int nt = 0; nt < 8; nt++) {
        int c = nt*8 + 2*tig;
        *(unsigned*)(Clo + c) = h2u(__floats2half2_rn(o[nt][0]*il, o[nt][1]*il));
        *(unsigned*)(Chi + c) = h2u(__floats2half2_rn(o[nt][2]*ih, o[nt][3]*ih));
    }
}

// ---------------- launch ----------------
extern "C" void kernel_launch(void* const* d_in, const int* in_sizes, int n_in,
                              void* d_out, int out_size) {
    const float* queries = (const float*)d_in[0];
    const float* keys    = (const float*)d_in[1];
    const float* values  = (const float*)d_in[2];
    const float* ln_q_g  = (const float*)d_in[3];
    const float* ln_q_b  = (const float*)d_in[4];
    const float* ln_k_g  = (const float*)d_in[5];
    const float* ln_k_b  = (const float*)d_in[6];
    const float* ln_v_g  = (const float*)d_in[7];
    const float* ln_v_b  = (const float*)d_in[8];
    const float* Wq = (const float*)d_in[9];   const float* bq = (const float*)d_in[10];
    const float* Wk = (const float*)d_in[11];  const float* bk = (const float*)d_in[12];
    const float* Wv = (const float*)d_in[13];  const float* bv = (const float*)d_in[14];
    const float* Wo = (const float*)d_in[15];  const float* bo = (const float*)d_in[16];
    const float* Ww1 = (const float*)d_in[17]; const float* bw1 = (const float*)d_in[18];
    const float* Ww2 = (const float*)d_in[19]; const float* bw2 = (const float*)d_in[20];
    float* out = (float*)d_out;

    float *QN, *HID;
    __half *QNh, *KNh, *VNh, *Wqh, *Wkh, *Wvh, *Woh, *Qhh, *Khh, *Vhh, *CTXh;
    cudaGetSymbolAddress((void**)&QN, g_QN);
    cudaGetSymbolAddress((void**)&HID, g_HID);
    cudaGetSymbolAddress((void**)&QNh, g_QNh);
    cudaGetSymbolAddress((void**)&KNh, g_KNh);
    cudaGetSymbolAddress((void**)&VNh, g_VNh);
    cudaGetSymbolAddress((void**)&Wqh, g_Wqh);
    cudaGetSymbolAddress((void**)&Wkh, g_Wkh);
    cudaGetSymbolAddress((void**)&Wvh, g_Wvh);
    cudaGetSymbolAddress((void**)&Woh, g_Woh);
    cudaGetSymbolAddress((void**)&Qhh, g_Qhh);
    cudaGetSymbolAddress((void**)&Khh, g_Khh);
    cudaGetSymbolAddress((void**)&Vhh, g_Vhh);
    cudaGetSymbolAddress((void**)&CTXh, g_CTXh);

    init_kernel<<<1, 128>>>();
    ln_warp_kernel<<<NROWS/8, 256>>>(queries, ln_q_g, ln_q_b, QN, QNh, 1);
    ln_warp_kernel<<<NROWS/8, 256>>>(keys,    ln_k_g, ln_k_b, nullptr, KNh, 0);
    ln_warp_kernel<<<NROWS/8, 256>>>(values,  ln_v_g, ln_v_b, nullptr, VNh, 0);

    // weights fp32 -> half (one-shot each call; deterministic)
    wconv_kernel<<<DD*DD/4/256, 256>>>(Wq, Wqh);
    wconv_kernel<<<DD*DD/4/256, 256>>>(Wk, Wkh);
    wconv_kernel<<<DD*DD/4/256, 256>>>(Wv, Wvh);
    wconv_kernel<<<DD*DD/4/256, 256>>>(Wo, Woh);

    // window MLP hidden (fp32 — rintf-sensitive path)
    gemm_kernel<<<dim3(2, 64), 256>>>(QN, Ww1, bw1, HID, 128, 1);
    winred_kernel<<<NROWS, 128>>>(Ww2, bw2);

    dm_kernel<<<NROWS, 256>>>();
    batchstat_kernel<<<BB, 1024>>>();
    kp_kernel<<<BB, 1024>>>();
    gumbel_kernel<<<BB * 4, 512>>>();
    maskbuild_kernel<<<NROWS, 64>>>();
    needed_kernel<<<1, 32>>>();
    fill_kernel<<<(BB * NRAND) / 256, 256>>>();

    // projections (fp16 MMA; Q pre-scaled 1/8)
    gemm_h_kernel<<<dim3(8, 64), 128>>>(QNh, Wqh, bq, nullptr, nullptr, Qhh, 0.125f);
    gemm_h_kernel<<<dim3(8, 64), 128>>>(KNh, Wkh, bk, nullptr, nullptr, Khh, 1.0f);
    gemm_h_kernel<<<dim3(8, 64), 128>>>(VNh, Wvh, bv, nullptr, nullptr, Vhh, 1.0f);

    // V transpose for PV B-fragments
    vtrans_kernel<<<dim3(NROWS/32, DD/32), 256>>>();

    // attention (fp16 MMA flash, q-tile 128)
    attn_h2_kernel<<<dim3(SS / 128, BB * HH), 256>>>();

    // output projection + residual (fp16 MMA, fp32 out)
    gemm_h_kernel<<<dim3(8, 64), 128>>>(CTXh, Woh, bo, queries, out, nullptr, 0.0f);
}

// round 9
// speedup vs baseline: 4.3444x; 1.1159x over previous
#include <cuda_runtime.h>
#include <cuda_bf16.h>
#include <cuda_fp16.h>
#include <math.h>
#include <stdint.h>

// ---------------- problem constants ----------------
#define BB 2
#define SS 2048
#define DD 512
#define HH 8
#define NROWS (BB*SS)            // 4096
#define MWORDS (SS/32)           // 64
#define NRAND (SS*SS/2)          // 2097152 (power of two)
#define NEG_HUGE (-3.4028234663852886e38f)
#define TINYF 1.17549435e-38f

#define TF_PARTITIONABLE 1

// ---------------- scratch (device globals; no runtime alloc) ----------------
__device__ float  g_QN[NROWS*DD];          // fp32 qn (mask path)
__device__ __half g_QNh[NROWS*DD];
__device__ __half g_KNh[NROWS*DD];
__device__ __half g_VNh[NROWS*DD];
__device__ __half g_Wqh[DD*DD], g_Wkh[DD*DD], g_Wvh[DD*DD], g_Woh[DD*DD];
__device__ __half g_Qhh[NROWS*DD];         // Q proj, pre-scaled 1/8
__device__ __half g_Khh[NROWS*DD];
__device__ __half g_Vhh[NROWS*DD];
__device__ __half g_VTh[NROWS*DD];         // [(b*8+h)*64 + d]*2048 + s
__device__ __half g_CTXh[NROWS*DD];
__device__ float  g_HID[NROWS*128];
__device__ unsigned g_MASK[NROWS*MWORDS];
__device__ float g_DM[NROWS], g_CH[NROWS], g_MAG[NROWS], g_VAR1[NROWS], g_IMP[NROWS];
__device__ int   g_WIN[NROWS];
__device__ unsigned char g_KPB[NROWS];
__device__ unsigned g_KPW[BB*MWORDS];
__device__ unsigned g_CSW[BB*MWORDS];
__device__ float g_THR[BB], g_COMP[BB], g_IMPLO[BB], g_IMPHI[BB];
__device__ int   g_HASKP[BB], g_COUNT[BB], g_NEEDED[BB];
__device__ unsigned g_KEY_G[2], g_KEY_Q[2], g_KEY_K[2];

// ---------------- threefry-2x32 (JAX 20-round) ----------------
__device__ __forceinline__ void tf2x32(unsigned k0, unsigned k1, unsigned x0, unsigned x1,
                                       unsigned &o0, unsigned &o1) {
    unsigned ks2 = k0 ^ k1 ^ 0x1BD11BDAu;
    x0 += k0; x1 += k1;
#define TFR(r) { x0 += x1; x1 = (x1 << r) | (x1 >> (32 - r)); x1 ^= x0; }
    TFR(13) TFR(15) TFR(26) TFR(6)
    x0 += k1;  x1 += ks2 + 1u;
    TFR(17) TFR(29) TFR(16) TFR(24)
    x0 += ks2; x1 += k0 + 2u;
    TFR(13) TFR(15) TFR(26) TFR(6)
    x0 += k0;  x1 += k1 + 3u;
    TFR(17) TFR(29) TFR(16) TFR(24)
    x0 += k1;  x1 += ks2 + 4u;
    TFR(13) TFR(15) TFR(26) TFR(6)
    x0 += ks2; x1 += k0 + 5u;
#undef TFR
    o0 = x0; o1 = x1;
}

__device__ __forceinline__ unsigned tf_bits(unsigned k0, unsigned k1,
                                            unsigned long long idx,
                                            unsigned long long total) {
#if TF_PARTITIONABLE
    unsigned o0, o1;
    tf2x32(k0, k1, (unsigned)(idx >> 32), (unsigned)idx, o0, o1);
    return o0 ^ o1;
#else
    unsigned long long half = (total + 1ull) / 2ull;
    unsigned o0, o1;
    if (idx < half) { tf2x32(k0, k1, (unsigned)idx, (unsigned)(idx + half), o0, o1); return o0; }
    else            { tf2x32(k0, k1, (unsigned)(idx - half), (unsigned)idx, o0, o1); return o1; }
#endif
}

// ---------------- fp16 MMA + cp.async helpers ----------------
__device__ __forceinline__ void mma_f16(float d[4], const unsigned a[4],
                                        unsigned b0, unsigned b1) {
    asm volatile("mma.sync.aligned.m16n8k16.row.col.f32.f16.f16.f32 "
        "{%0,%1,%2,%3}, {%4,%5,%6,%7}, {%8,%9}, {%0,%1,%2,%3};"
        : "+f"(d[0]), "+f"(d[1]), "+f"(d[2]), "+f"(d[3])
        : "r"(a[0]), "r"(a[1]), "r"(a[2]), "r"(a[3]), "r"(b0), "r"(b1));
}
__device__ __forceinline__ unsigned h2u(__half2 h) { return *(unsigned*)&h; }

__device__ __forceinline__ void cp_async16(void* smem_dst, const void* gmem_src) {
    unsigned d = (unsigned)__cvta_generic_to_shared(smem_dst);
    asm volatile("cp.async.ca.shared.global [%0], [%1], 16;" :: "r"(d), "l"(gmem_src));
}
__device__ __forceinline__ void cp_commit() { asm volatile("cp.async.commit_group;"); }
template <int N>
__device__ __forceinline__ void cp_wait() { asm volatile("cp.async.wait_group %0;" :: "n"(N)); }

// ---------------- block reductions ----------------
__device__ __forceinline__ float bredSum(float v, float* s, int n) {
    int t = threadIdx.x; s[t] = v; __syncthreads();
    for (int k = n >> 1; k > 0; k >>= 1) { if (t < k) s[t] += s[t + k]; __syncthreads(); }
    float r = s[0]; __syncthreads(); return r;
}
__device__ __forceinline__ float bredMax(float v, float* s, int n) {
    int t = threadIdx.x; s[t] = v; __syncthreads();
    for (int k = n >> 1; k > 0; k >>= 1) { if (t < k) s[t] = fmaxf(s[t], s[t + k]); __syncthreads(); }
    float r = s[0]; __syncthreads(); return r;
}
__device__ __forceinline__ float bredMin(float v, float* s, int n) {
    int t = threadIdx.x; s[t] = v; __syncthreads();
    for (int k = n >> 1; k > 0; k >>= 1) { if (t < k) s[t] = fminf(s[t], s[t + k]); __syncthreads(); }
    float r = s[0]; __syncthreads(); return r;
}

// ---------------- init ----------------
__global__ void init_kernel() {
    int t = blockIdx.x * blockDim.x + threadIdx.x;
    if (t < BB*MWORDS) g_CSW[t] = 0u;
    if (t < BB) g_COUNT[t] = 0;
    if (t == 0) {
        unsigned o0, o1, a0, a1;
        tf2x32(0u, 42u, 0u, 0u, o0, o1); g_KEY_G[0] = o0; g_KEY_G[1] = o1;
#if TF_PARTITIONABLE
        tf2x32(0u, 42u, 0u, 1u, o0, o1);
        tf2x32(o0, o1, 0u, 1u, a0, a1); g_KEY_Q[0] = a0; g_KEY_Q[1] = a1;
        tf2x32(0u, 42u, 0u, 2u, o0, o1);
        tf2x32(o0, o1, 0u, 1u, a0, a1); g_KEY_K[0] = a0; g_KEY_K[1] = a1;
#else
        unsigned p0, p1, q0, q1;
        tf2x32(0u, 42u, 0u, 1u, o0, o1);
        tf2x32(o0, o1, 0u, 2u, p0, p1);
        tf2x32(o0, o1, 1u, 3u, q0, q1);
        g_KEY_Q[0] = p1; g_KEY_Q[1] = q1;
        tf2x32(0u, 42u, 0u, 2u, o0, o1);
        tf2x32(o0, o1, 0u, 2u, p0, p1);
        tf2x32(o0, o1, 1u, 3u, q0, q1);
        g_KEY_K[0] = p1; g_KEY_K[1] = q1;
#endif
    }
}

// ---------------- fused LayerNorm (q/k/v in one launch) ----------------
__global__ void ln3_kernel(const float* __restrict__ xq, const float* __restrict__ xk,
                           const float* __restrict__ xv,
                           const float* __restrict__ gq, const float* __restrict__ bq_,
                           const float* __restrict__ gk, const float* __restrict__ bk_,
                           const float* __restrict__ gv, const float* __restrict__ bv_) {
    int z = blockIdx.y;
    const float* x  = (z == 0) ? xq : (z == 1) ? xk : xv;
    const float* gam = (z == 0) ? gq : (z == 1) ? gk : gv;
    const float* bet = (z == 0) ? bq_ : (z == 1) ? bk_ : bv_;
    __half* yh = (z == 0) ? g_QNh : (z == 1) ? g_KNh : g_VNh;
    int w = threadIdx.x >> 5, lane = threadIdx.x & 31;
    int row = blockIdx.x * 8 + w;
    const float4* xr = (const float4*)(x + (size_t)row * 512);
    float4 v[4];
#pragma unroll
    for (int j = 0; j < 4; j++) v[j] = xr[lane + j * 32];
    float s = 0.f;
#pragma unroll
    for (int j = 0; j < 4; j++) s += v[j].x + v[j].y + v[j].z + v[j].w;
#pragma unroll
    for (int o = 16; o > 0; o >>= 1) s += __shfl_xor_sync(0xffffffffu, s, o);
    float mu = s * (1.f / 512.f);
    float qv = 0.f;
#pragma unroll
    for (int j = 0; j < 4; j++) {
        float a = v[j].x - mu, b = v[j].y - mu, c = v[j].z - mu, d = v[j].w - mu;
        qv += a * a + b * b + c * c + d * d;
    }
#pragma unroll
    for (int o = 16; o > 0; o >>= 1) qv += __shfl_xor_sync(0xffffffffu, qv, o);
    float r = rsqrtf(qv * (1.f / 512.f) + 1e-5f);
    const float4* g4 = (const float4*)gam;
    const float4* b4 = (const float4*)bet;
    float yv[16];
#pragma unroll
    for (int j = 0; j < 4; j++) {
        float4 gg = g4[lane + j * 32], bb = b4[lane + j * 32];
        float4 o4;
        o4.x = (v[j].x - mu) * r * gg.x + bb.x;
        o4.y = (v[j].y - mu) * r * gg.y + bb.y;
        o4.z = (v[j].z - mu) * r * gg.z + bb.z;
        o4.w = (v[j].w - mu) * r * gg.w + bb.w;
        if (z == 0) ((float4*)(g_QN + (size_t)row * 512))[lane + j * 32] = o4;
        __half2 h01 = __floats2half2_rn(o4.x, o4.y);
        __half2 h23 = __floats2half2_rn(o4.z, o4.w);
        *(uint2*)(yh + (size_t)row * 512 + (lane + j * 32) * 4) =
            make_uint2(h2u(h01), h2u(h23));
        yv[j*4+0] = o4.x; yv[j*4+1] = o4.y; yv[j*4+2] = o4.z; yv[j*4+3] = o4.w;
    }
    if (z == 0) {
        float sq = 0.f, sy = 0.f;
#pragma unroll
        for (int i = 0; i < 16; i++) { sq += yv[i] * yv[i]; sy += yv[i]; }
#pragma unroll
        for (int o = 16; o > 0; o >>= 1) {
            sq += __shfl_xor_sync(0xffffffffu, sq, o);
            sy += __shfl_xor_sync(0xffffffffu, sy, o);
        }
        float my = sy * (1.f / 512.f);
        float sd = 0.f;
#pragma unroll
        for (int i = 0; i < 16; i++) { float e = yv[i] - my; sd += e * e; }
#pragma unroll
        for (int o = 16; o > 0; o >>= 1) sd += __shfl_xor_sync(0xffffffffu, sd, o);
        if (lane == 0) { g_MAG[row] = sqrtf(sq); g_VAR1[row] = sd * (1.f / 511.f); }
    }
}

// ---------------- fused weight conversion (4 matrices, one launch) -------------
__global__ void wconv4_kernel(const float* __restrict__ Wq, const float* __restrict__ Wk,
                              const float* __restrict__ Wv, const float* __restrict__ Wo) {
    int z = blockIdx.y;
    const float* W = (z == 0) ? Wq : (z == 1) ? Wk : (z == 2) ? Wv : Wo;
    __half* Wh = (z == 0) ? g_Wqh : (z == 1) ? g_Wkh : (z == 2) ? g_Wvh : g_Woh;
    int i = (blockIdx.x * blockDim.x + threadIdx.x) * 4;
    float4 v = *(const float4*)(W + i);
    __half2 h01 = __floats2half2_rn(v.x, v.y);
    __half2 h23 = __floats2half2_rn(v.z, v.w);
    *(uint2*)(Wh + i) = make_uint2(h2u(h01), h2u(h23));
}

// ---------------- fp32 GEMM (window-MLP hidden only; rintf-sensitive) ---------
__global__ void gemm_kernel(const float* __restrict__ A, const float* __restrict__ W,
                            const float* __restrict__ bias, float* __restrict__ C,
                            int N, int doRelu) {
    __shared__ float As[64][17];
    __shared__ float Ws[64][17];
    int row0 = blockIdx.y * 64;
    int col0 = blockIdx.x * 64;
    int tid = threadIdx.x;
    int tx = tid & 15, ty = tid >> 4;
    int r0 = ty * 4, c0 = tx * 4;
    int lr = tid >> 2, lc4 = (tid & 3) * 4;
    float acc[4][4] = {};
    for (int kk = 0; kk < 512; kk += 16) {
        float4 av = *reinterpret_cast<const float4*>(A + (size_t)(row0 + lr) * 512 + kk + lc4);
        float4 wv = *reinterpret_cast<const float4*>(W + (size_t)(col0 + lr) * 512 + kk + lc4);
        As[lr][lc4] = av.x; As[lr][lc4+1] = av.y; As[lr][lc4+2] = av.z; As[lr][lc4+3] = av.w;
        Ws[lr][lc4] = wv.x; Ws[lr][lc4+1] = wv.y; Ws[lr][lc4+2] = wv.z; Ws[lr][lc4+3] = wv.w;
        __syncthreads();
#pragma unroll
        for (int kc = 0; kc < 16; kc++) {
            float a0 = As[r0][kc], a1 = As[r0+1][kc], a2 = As[r0+2][kc], a3 = As[r0+3][kc];
            float b0 = Ws[c0][kc], b1 = Ws[c0+1][kc], b2 = Ws[c0+2][kc], b3 = Ws[c0+3][kc];
            acc[0][0] += a0*b0; acc[0][1] += a0*b1; acc[0][2] += a0*b2; acc[0][3] += a0*b3;
            acc[1][0] += a1*b0; acc[1][1] += a1*b1; acc[1][2] += a1*b2; acc[1][3] += a1*b3;
            acc[2][0] += a2*b0; acc[2][1] += a2*b1; acc[2][2] += a2*b2; acc[2][3] += a2*b3;
            acc[3][0] += a3*b0; acc[3][1] += a3*b1; acc[3][2] += a3*b2; acc[3][3] += a3*b3;
        }
        __syncthreads();
    }
#pragma unroll
    for (int i = 0; i < 4; i++) {
#pragma unroll
        for (int j = 0; j < 4; j++) {
            int col = col0 + c0 + j;
            size_t ro = (size_t)(row0 + r0 + i);
            float v = acc[i][j] + bias[col];
            if (doRelu) v = fmaxf(v, 0.f);
            C[ro * (size_t)N + col] = v;
        }
    }
}

// ---------------- fused QKV fp16 MMA GEMM (grid.z selects operand set) ---------
#define GS 40
__global__ void __launch_bounds__(128) qkv_h_kernel(
        const float* __restrict__ bq_, const float* __restrict__ bk_,
        const float* __restrict__ bv_) {
    int z = blockIdx.z;
    const __half* A = (z == 0) ? g_QNh : (z == 1) ? g_KNh : g_VNh;
    const __half* W = (z == 0) ? g_Wqh : (z == 1) ? g_Wkh : g_Wvh;
    const float* bias = (z == 0) ? bq_ : (z == 1) ? bk_ : bv_;
    __half* Ch = (z == 0) ? g_Qhh : (z == 1) ? g_Khh : g_Vhh;
    float oscale = (z == 0) ? 0.125f : 1.0f;

    __shared__ __half As[64*GS];
    __shared__ __half Ws[64*GS];
    int tid = threadIdx.x;
    int w = tid >> 5, lane = tid & 31, g = lane >> 2, tig = lane & 3;
    int col0 = blockIdx.x * 64, row0 = blockIdx.y * 64;
    int wq = w * 16;
    float acc[8][4];
#pragma unroll
    for (int nt = 0; nt < 8; nt++) { acc[nt][0]=0; acc[nt][1]=0; acc[nt][2]=0; acc[nt][3]=0; }
    for (int kc = 0; kc < 512; kc += 32) {
#pragma unroll
        for (int it = 0; it < 2; it++) {
            int idx = tid + it * 128;
            int r = idx >> 2, c8 = (idx & 3) * 8;
            *(uint4*)&As[r*GS + c8] = *(const uint4*)&A[(size_t)(row0 + r) * 512 + kc + c8];
            *(uint4*)&Ws[r*GS + c8] = *(const uint4*)&W[(size_t)(col0 + r) * 512 + kc + c8];
        }
        __syncthreads();
#pragma unroll
        for (int ks = 0; ks < 2; ks++) {
            unsigned a[4];
            a[0] = *(unsigned*)&As[(wq+g)*GS   + ks*16 + 2*tig];
            a[1] = *(unsigned*)&As[(wq+g+8)*GS + ks*16 + 2*tig];
            a[2] = *(unsigned*)&As[(wq+g)*GS   + ks*16 + 8 + 2*tig];
            a[3] = *(unsigned*)&As[(wq+g+8)*GS + ks*16 + 8 + 2*tig];
#pragma unroll
            for (int nt = 0; nt < 8; nt++) {
                unsigned b0 = *(unsigned*)&Ws[(nt*8+g)*GS + ks*16 + 2*tig];
                unsigned b1 = *(unsigned*)&Ws[(nt*8+g)*GS + ks*16 + 8 + 2*tig];
                mma_f16(acc[nt], a, b0, b1);
            }
        }
        __syncthreads();
    }
    int rlo = row0 + wq + g, rhi = rlo + 8;
#pragma unroll
    for (int nt = 0; nt < 8; nt++) {
        int c = col0 + nt*8 + 2*tig;
        float v0 = acc[nt][0] + bias[c],   v1 = acc[nt][1] + bias[c+1];
        float v2 = acc[nt][2] + bias[c],   v3 = acc[nt][3] + bias[c+1];
        __half2 lo = __floats2half2_rn(v0 * oscale, v1 * oscale);
        __half2 hi = __floats2half2_rn(v2 * oscale, v3 * oscale);
        *(unsigned*)&Ch[(size_t)rlo * 512 + c] = h2u(lo);
        *(unsigned*)&Ch[(size_t)rhi * 512 + c] = h2u(hi);
    }
}

// ---------------- O-projection (half in, fp32 out + residual) ------------------
__global__ void __launch_bounds__(128) oproj_h_kernel(
        const float* __restrict__ bias, const float* __restrict__ resid,
        float* __restrict__ Cf) {
    __shared__ __half As[64*GS];
    __shared__ __half Ws[64*GS];
    int tid = threadIdx.x;
    int w = tid >> 5, lane = tid & 31, g = lane >> 2, tig = lane & 3;
    int col0 = blockIdx.x * 64, row0 = blockIdx.y * 64;
    int wq = w * 16;
    float acc[8][4];
#pragma unroll
    for (int nt = 0; nt < 8; nt++) { acc[nt][0]=0; acc[nt][1]=0; acc[nt][2]=0; acc[nt][3]=0; }
    for (int kc = 0; kc < 512; kc += 32) {
#pragma unroll
        for (int it = 0; it < 2; it++) {
            int idx = tid + it * 128;
            int r = idx >> 2, c8 = (idx & 3) * 8;
            *(uint4*)&As[r*GS + c8] = *(const uint4*)&g_CTXh[(size_t)(row0 + r) * 512 + kc + c8];
            *(uint4*)&Ws[r*GS + c8] = *(const uint4*)&g_Woh[(size_t)(col0 + r) * 512 + kc + c8];
        }
        __syncthreads();
#pragma unroll
        for (int ks = 0; ks < 2; ks++) {
            unsigned a[4];
            a[0] = *(unsigned*)&As[(wq+g)*GS   + ks*16 + 2*tig];
            a[1] = *(unsigned*)&As[(wq+g+8)*GS + ks*16 + 2*tig];
            a[2] = *(unsigned*)&As[(wq+g)*GS   + ks*16 + 8 + 2*tig];
            a[3] = *(unsigned*)&As[(wq+g+8)*GS + ks*16 + 8 + 2*tig];
#pragma unroll
            for (int nt = 0; nt < 8; nt++) {
                unsigned b0 = *(unsigned*)&Ws[(nt*8+g)*GS + ks*16 + 2*tig];
                unsigned b1 = *(unsigned*)&Ws[(nt*8+g)*GS + ks*16 + 8 + 2*tig];
                mma_f16(acc[nt], a, b0, b1);
            }
        }
        __syncthreads();
    }
    int rlo = row0 + wq + g, rhi = rlo + 8;
#pragma unroll
    for (int nt = 0; nt < 8; nt++) {
        int c = col0 + nt*8 + 2*tig;
        float v0 = acc[nt][0] + bias[c] + resid[(size_t)rlo * 512 + c];
        float v1 = acc[nt][1] + bias[c+1] + resid[(size_t)rlo * 512 + c + 1];
        float v2 = acc[nt][2] + bias[c] + resid[(size_t)rhi * 512 + c];
        float v3 = acc[nt][3] + bias[c+1] + resid[(size_t)rhi * 512 + c + 1];
        Cf[(size_t)rlo * 512 + c] = v0; Cf[(size_t)rlo * 512 + c + 1] = v1;
        Cf[(size_t)rhi * 512 + c] = v2; Cf[(size_t)rhi * 512 + c + 1] = v3;
    }
}

// ---------------- V transpose ----------------
__global__ void vtrans_kernel() {
    __shared__ __half t[32][33];
    int r0 = blockIdx.x * 32;
    int c0 = blockIdx.y * 32;
    int tx = threadIdx.x & 31, ty = threadIdx.x >> 5;
#pragma unroll
    for (int i = 0; i < 4; i++)
        t[ty + 8*i][tx] = g_Vhh[(size_t)(r0 + ty + 8*i) * 512 + c0 + tx];
    __syncthreads();
    int b = r0 >> 11;
    int h = c0 >> 6, d0 = c0 & 63;
#pragma unroll
    for (int i = 0; i < 4; i++) {
        int d = d0 + ty + 8*i;
        g_VTh[((size_t)(b * 8 + h) * 64 + d) * 2048 + (r0 & 2047) + tx] = t[tx][ty + 8*i];
    }
}

// ---------------- window reduce ----------------
__global__ void winred_kernel(const float* __restrict__ W2, const float* __restrict__ b2) {
    __shared__ float sb[128];
    int row = blockIdx.x, tid = threadIdx.x;
    sb[tid] = g_HID[(size_t)row * 128 + tid] * W2[tid];
    __syncthreads();
    for (int st = 64; st > 0; st >>= 1) { if (tid < st) sb[tid] += sb[tid + st]; __syncthreads(); }
    if (tid == 0) {
        float s = sb[0] + b2[0];
        float adj = 0.5f + 1.0f / (1.0f + expf(-s));
        int w = (int)rintf(64.0f * adj);
        g_WIN[row] = min(max(w, 1), 128);
    }
}

// ---------------- dm/ch/imp ----------------
__global__ void dm_kernel() {
    __shared__ float sb[256];
    int row = blockIdx.x, tid = threadIdx.x;
    int t = row & (SS - 1);
    const float* q0 = g_QN + (size_t)row * DD;
    float acc = 0.f, chs = 0.f;
    const int   sv[4] = {1, 2, 3, 5};
    const float wv[4] = {0.4f, 0.3f, 0.2f, 0.1f};
    for (int l = 0; l < 2; l++) {
        int d = tid + l * 256;
        float base = q0[d];
#pragma unroll
        for (int si = 0; si < 4; si++) {
            int s = sv[si];
            if (t + s < SS)
                acc += wv[si] * (fabsf(q0[(size_t)s * DD + d] - base) / (float)s);
        }
        if (t < SS - 1) chs += fabsf(q0[DD + d] - base);
    }
    float a = bredSum(acc, sb, 256);
    float c = bredSum(chs, sb, 256);
    if (tid == 0) {
        float chv = c * (1.f / 512.f);
        g_DM[row] = a * (1.f / 512.f);
        g_CH[row] = chv;
        g_IMP[row] = 0.5f * g_MAG[row] + 0.5f * chv;
    }
}

// ---------------- per-batch stats ----------------
__global__ void batchstat_kernel() {
    __shared__ float sb[1024];
    int b = blockIdx.x, tid = threadIdx.x;
    int r0 = b * SS + tid, r1 = r0 + 1024;
    float d0 = g_DM[r0], d1 = g_DM[r1];
    float mean = bredSum(d0 + d1, sb, 1024) * (1.f / 2048.f);
    float e0 = d0 - mean, e1 = d1 - mean;
    float var = bredSum(e0 * e0 + e1 * e1, sb, 1024) * (1.f / 2047.f);
    float comp = bredSum(g_VAR1[r0] + g_VAR1[r1], sb, 1024) * (1.f / 2048.f);
    float i0 = g_IMP[r0], i1 = g_IMP[r1];
    float lo = bredMin(fminf(i0, i1), sb, 1024);
    float hi = bredMax(fmaxf(i0, i1), sb, 1024);
    if (tid == 0) {
        g_THR[b] = mean + 0.5f * sqrtf(var);
        g_COMP[b] = comp;
        g_IMPLO[b] = lo; g_IMPHI[b] = hi;
    }
}

// ---------------- keypoints ----------------
__global__ void kp_kernel() {
    __shared__ unsigned char kpf[SS];
    __shared__ int anyf;
    int b = blockIdx.x, tid = threadIdx.x;
    if (tid == 0) anyf = 0;
    __syncthreads();
    float thr = g_THR[b];
    for (int it = 0; it < 2; it++) {
        int t = tid + it * 1024;
        int row = b * SS + t;
        float dm = g_DM[row];
        float left  = (t > 0)      ? g_DM[row - 1] : -1.0f;
        float right = (t < SS - 1) ? g_DM[row + 1] : -1.0f;
        int kp = (dm > thr) && (dm > left) && (dm > right);
        if (t == 0 || t == SS - 1) kp = kp || (dm > thr);
        kpf[t] = (unsigned char)kp;
        g_KPB[row] = (unsigned char)kp;
        if (kp) anyf = 1;
    }
    __syncthreads();
    if (tid < MWORDS) {
        unsigned w = 0;
        for (int j = 0; j < 32; j++) if (kpf[tid * 32 + j]) w |= (1u << j);
        g_KPW[b * MWORDS + tid] = w;
    }
    if (tid == 0) g_HASKP[b] = anyf;
}

// ---------------- stratified gumbel top-4 ----------------
__global__ void gumbel_kernel() {
    __shared__ float sb[512];
    __shared__ float lv[512];
    __shared__ int si[512];
    int seg = blockIdx.x;
    int b = seg >> 2, l = seg & 3;
    int tid = threadIdx.x;
    int t = l * 512 + tid;
    int row = b * SS + t;
    float lo = g_IMPLO[b], hi = g_IMPHI[b];
    float ip = (g_IMP[row] - lo) / (hi - lo + 1e-6f);
    float ssum = bredSum(ip, sb, 512);
    float prob = ip / (ssum + 1e-6f);
    unsigned bits = tf_bits(g_KEY_G[0], g_KEY_G[1], (unsigned long long)(seg * 512 + tid), 4096ull);
    float f = __uint_as_float((bits >> 9) | 0x3f800000u) - 1.0f;
    float u = fmaxf(TINYF, f * (1.0f - TINYF) + TINYF);
    float gum = -logf(-logf(u));
    lv[tid] = logf(prob + 1e-20f) + gum;
    __syncthreads();
    for (int round = 0; round < 4; round++) {
        sb[tid] = lv[tid]; si[tid] = tid;
        __syncthreads();
        for (int st = 256; st > 0; st >>= 1) {
            if (tid < st) {
                float ov = sb[tid + st]; int oi = si[tid + st];
                if (ov > sb[tid] || (ov == sb[tid] && oi < si[tid])) { sb[tid] = ov; si[tid] = oi; }
            }
            __syncthreads();
        }
        if (tid == 0) {
            int sel = si[0];
            int tt = l * 512 + sel;
            atomicOr(&g_CSW[b * MWORDS + (tt >> 5)], 1u << (tt & 31));
            lv[sel] = -INFINITY;
        }
        __syncthreads();
    }
}

// ---------------- mask build + density ----------------
__device__ __forceinline__ unsigned range_word(int lo, int hi, int kb) {
    int a = lo - kb, e = hi - kb;
    if (e < 0 || a > 31) return 0u;
    a = max(a, 0); e = min(e, 31);
    unsigned m = (e == 31) ? 0xFFFFFFFFu : ((1u << (e + 1)) - 1u);
    return m & (0xFFFFFFFFu << a);
}

__global__ void maskbuild_kernel() {
    int row = blockIdx.x;
    int b = row >> 11, q = row & (SS - 1);
    int w = threadIdx.x;
    int kb = w * 32;
    int win = g_WIN[row];
    unsigned m = range_word(max(q - win, 0), min(q + win, SS - 1), kb);
    if (g_HASKP[b]) {
        m |= g_KPB[row] ? 0xFFFFFFFFu : g_KPW[b * MWORDS + w];
    } else {
        unsigned fbw = ((w == 0) ? 1u : 0u) | (((w & 15) == 15) ? 0x80000000u : 0u);
        int qin = (q == 0 || q == 511 || q == 1023 || q == 1535 || q == 2047);
        m |= qin ? 0xFFFFFFFFu : fbw;
    }
    m |= g_CSW[b * MWORDS + w];
    g_MASK[(size_t)row * MWORDS + w] = m;
    int pc = __popc(m);
#pragma unroll
    for (int o = 16; o > 0; o >>= 1) pc += __shfl_down_sync(0xffffffffu, pc, o);
    __shared__ int ws[2];
    if ((w & 31) == 0) ws[w >> 5] = pc;
    __syncthreads();
    if (w == 0) atomicAdd(&g_COUNT[b], ws[0] + ws[1]);
}

// ---------------- needed ----------------
__global__ void needed_kernel() {
    if (threadIdx.x == 0) {
        float c0 = g_COMP[0], c1 = g_COMP[1];
        float mn = fminf(c0, c1), mx = fmaxf(c0, c1);
        for (int b = 0; b < BB; b++) {
            float nc = (g_COMP[b] - mn) / (mx - mn + 1e-6f);
            float ratio = fminf(fmaxf(0.3f * (0.5f + nc), 0.1f), 0.5f);
            float dens = (float)g_COUNT[b] / 4194304.0f;
            float nd = ceilf((ratio - dens) * 4194304.0f);
            int n = (int)nd;
            g_NEEDED[b] = max(n, 0);
        }
    }
}

// ---------------- random fill (grid-stride) ----------------
__global__ void fill_kernel() {
    const unsigned long long total = (unsigned long long)BB * NRAND;
    unsigned long long stride = (unsigned long long)gridDim.x * blockDim.x;
    for (unsigned long long j = (unsigned long long)blockIdx.x * blockDim.x + threadIdx.x;
         j < total; j += stride) {
        int b = (int)(j >> 21);
        int i = (int)(j & (NRAND - 1));
        if (i < g_NEEDED[b]) {
            unsigned qb = tf_bits(g_KEY_Q[0], g_KEY_Q[1], j, total);
            unsigned kb = tf_bits(g_KEY_K[0], g_KEY_K[1], j, total);
            int qr = qb & (SS - 1), kr = kb & (SS - 1);
            atomicOr(&g_MASK[((size_t)(b * SS + qr)) * MWORDS + (kr >> 5)], 1u << (kr & 31));
        }
    }
}

// ---------------- flash attention, fp16 MMA, cp.async double buffer -------------
#define AT_STR 72
__global__ void __launch_bounds__(256) attn_h2_kernel() {
    __shared__ __half Ks[2][64*AT_STR];
    __shared__ __half VT[2][64*AT_STR];
    int tid = threadIdx.x;
    int w = tid >> 5, lane = tid & 31;
    int g = lane >> 2, tig = lane & 3;
    int qt = blockIdx.x, bh = blockIdx.y;
    int b = bh >> 3, h = bh & 7;
    int q0 = qt * 128, wq = w * 16;
    size_t qlo_row = (size_t)(b * SS + q0 + wq + g);
    size_t qhi_row = qlo_row + 8;

    const __half* Kbase  = g_Khh + ((size_t)(b * SS)) * 512 + h * 64;
    const __half* VTbase = g_VTh + ((size_t)bh * 64) * 2048;

    int st_r = tid >> 3, st_c8 = (tid & 7) * 8;       // 32 rows per pass, 2 passes
    // stage tile k0 into buffer buf
    auto stage = [&](int k0, int buf) {
#pragma unroll
        for (int it = 0; it < 2; it++) {
            int r = st_r + it * 32;
            cp_async16(&Ks[buf][r*AT_STR + st_c8], Kbase + (size_t)(k0 + r) * 512 + st_c8);
            cp_async16(&VT[buf][r*AT_STR + st_c8], VTbase + (size_t)r * 2048 + k0 + st_c8);
        }
    };

    // Q fragments direct from global (half, pre-scaled 1/8)
    const __half* Qlo = g_Qhh + qlo_row * 512 + h * 64;
    const __half* Qhi = g_Qhh + qhi_row * 512 + h * 64;
    unsigned qa[4][4];
#pragma unroll
    for (int ks = 0; ks < 4; ks++) {
        qa[ks][0] = *(const unsigned*)(Qlo + ks*16 + 2*tig);
        qa[ks][1] = *(const unsigned*)(Qhi + ks*16 + 2*tig);
        qa[ks][2] = *(const unsigned*)(Qlo + ks*16 + 8 + 2*tig);
        qa[ks][3] = *(const unsigned*)(Qhi + ks*16 + 8 + 2*tig);
    }
    stage(0, 0); cp_commit();

    float o[8][4];
#pragma unroll
    for (int nt = 0; nt < 8; nt++) { o[nt][0]=0; o[nt][1]=0; o[nt][2]=0; o[nt][3]=0; }
    float m_lo = -INFINITY, m_hi = -INFINITY, l_lo = 0.f, l_hi = 0.f;
    const unsigned* mrow_lo = g_MASK + qlo_row * MWORDS;
    const unsigned* mrow_hi = g_MASK + qhi_row * MWORDS;

    for (int i = 0; i < 32; i++) {
        int cur = i & 1;
        int k0 = i * 64;
        if (i + 1 < 32) {
            stage((i + 1) * 64, 1 - cur); cp_commit();
            cp_wait<1>();
        } else {
            cp_wait<0>();
        }
        __syncthreads();
        // S = (Q/8) K^T
        float s[8][4];
#pragma unroll
        for (int nt = 0; nt < 8; nt++) { s[nt][0]=0; s[nt][1]=0; s[nt][2]=0; s[nt][3]=0; }
#pragma unroll
        for (int ks = 0; ks < 4; ks++) {
#pragma unroll
            for (int nt = 0; nt < 8; nt++) {
                unsigned b0 = *(unsigned*)&Ks[cur][(nt*8+g)*AT_STR + ks*16 + 2*tig];
                unsigned b1 = *(unsigned*)&Ks[cur][(nt*8+g)*AT_STR + ks*16 + 8 + 2*tig];
                mma_f16(s[nt], qa[ks], b0, b1);
            }
        }
        // mask (bit set => masked OUT)
        unsigned ml0 = mrow_lo[k0 >> 5], ml1 = mrow_lo[(k0 >> 5) + 1];
        unsigned mh0 = mrow_hi[k0 >> 5], mh1 = mrow_hi[(k0 >> 5) + 1];
#pragma unroll
        for (int nt = 0; nt < 8; nt++) {
            int cb = nt*8 + 2*tig;
            unsigned wl = (cb < 32) ? ml0 : ml1;
            unsigned wh = (cb < 32) ? mh0 : mh1;
            int bit = cb & 31;
            if ((wl >> bit) & 1)       s[nt][0] = NEG_HUGE;
            if ((wl >> (bit + 1)) & 1) s[nt][1] = NEG_HUGE;
            if ((wh >> bit) & 1)       s[nt][2] = NEG_HUGE;
            if ((wh >> (bit + 1)) & 1) s[nt][3] = NEG_HUGE;
        }
        // online softmax
        float tm_lo = -INFINITY, tm_hi = -INFINITY;
#pragma unroll
        for (int nt = 0; nt < 8; nt++) {
            tm_lo = fmaxf(tm_lo, fmaxf(s[nt][0], s[nt][1]));
            tm_hi = fmaxf(tm_hi, fmaxf(s[nt][2], s[nt][3]));
        }
        tm_lo = fmaxf(tm_lo, __shfl_xor_sync(0xffffffffu, tm_lo, 1));
        tm_lo = fmaxf(tm_lo, __shfl_xor_sync(0xffffffffu, tm_lo, 2));
        tm_hi = fmaxf(tm_hi, __shfl_xor_sync(0xffffffffu, tm_hi, 1));
        tm_hi = fmaxf(tm_hi, __shfl_xor_sync(0xffffffffu, tm_hi, 2));
        float mn_lo = fmaxf(m_lo, tm_lo), mn_hi = fmaxf(m_hi, tm_hi);
        float sc_lo = __expf(m_lo - mn_lo), sc_hi = __expf(m_hi - mn_hi);
        m_lo = mn_lo; m_hi = mn_hi;
        float rs_lo = 0.f, rs_hi = 0.f;
        unsigned ph[8][2];
#pragma unroll
        for (int nt = 0; nt < 8; nt++) {
            float p0 = __expf(s[nt][0] - m_lo);
            float p1 = __expf(s[nt][1] - m_lo);
            float p2 = __expf(s[nt][2] - m_hi);
            float p3 = __expf(s[nt][3] - m_hi);
            rs_lo += p0 + p1; rs_hi += p2 + p3;
            ph[nt][0] = h2u(__floats2half2_rn(p0, p1));
            ph[nt][1] = h2u(__floats2half2_rn(p2, p3));
            o[nt][0] *= sc_lo; o[nt][1] *= sc_lo; o[nt][2] *= sc_hi; o[nt][3] *= sc_hi;
        }
        rs_lo += __shfl_xor_sync(0xffffffffu, rs_lo, 1);
        rs_lo += __shfl_xor_sync(0xffffffffu, rs_lo, 2);
        rs_hi += __shfl_xor_sync(0xffffffffu, rs_hi, 1);
        rs_hi += __shfl_xor_sync(0xffffffffu, rs_hi, 2);
        l_lo = l_lo * sc_lo + rs_lo;
        l_hi = l_hi * sc_hi + rs_hi;
        // O += P V
#pragma unroll
        for (int ks = 0; ks < 4; ks++) {
            unsigned pa[4];
            pa[0] = ph[2*ks][0];
            pa[1] = ph[2*ks][1];
            pa[2] = ph[2*ks+1][0];
            pa[3] = ph[2*ks+1][1];
#pragma unroll
            for (int nt = 0; nt < 8; nt++) {
                unsigned b0 = *(unsigned*)&VT[cur][(nt*8+g)*AT_STR + ks*16 + 2*tig];
                unsigned b1 = *(unsigned*)&VT[cur][(nt*8+g)*AT_STR + ks*16 + 8 + 2*tig];
                mma_f16(o[nt], pa, b0, b1);
            }
        }
        __syncthreads();   // all warps done with buf[cur] before next stage overwrites it
    }
    float il = 1.f / l_lo, ih = 1.f / l_hi;
    __half* Clo = g_CTXh + qlo_row * 512 + h * 64;
    __half* Chi = g_CTXh + qhi_row * 512 + h * 64;
#pragma unroll
    for (int nt = 0; nt < 8; nt++) {
        int c = nt*8 + 2*tig;
        *(unsigned*)(Clo + c) = h2u(__floats2half2_rn(o[nt][0]*il, o[nt][1]*il));
        *(unsigned*)(Chi + c) = h2u(__floats2half2_rn(o[nt][2]*ih, o[nt][3]*ih));
    }
}

// ---------------- launch ----------------
extern "C" void kernel_launch(void* const* d_in, const int* in_sizes, int n_in,
                              void* d_out, int out_size) {
    const float* queries = (const float*)d_in[0];
    const float* keys    = (const float*)d_in[1];
    const float* values  = (const float*)d_in[2];
    const float* ln_q_g  = (const float*)d_in[3];
    const float* ln_q_b  = (const float*)d_in[4];
    const float* ln_k_g  = (const float*)d_in[5];
    const float* ln_k_b  = (const float*)d_in[6];
    const float* ln_v_g  = (const float*)d_in[7];
    const float* ln_v_b  = (const float*)d_in[8];
    const float* Wq = (const float*)d_in[9];   const float* bq = (const float*)d_in[10];
    const float* Wk = (const float*)d_in[11];  const float* bk = (const float*)d_in[12];
    const float* Wv = (const float*)d_in[13];  const float* bv = (const float*)d_in[14];
    const float* Wo = (const float*)d_in[15];  const float* bo = (const float*)d_in[16];
    const float* Ww1 = (const float*)d_in[17]; const float* bw1 = (const float*)d_in[18];
    const float* Ww2 = (const float*)d_in[19]; const float* bw2 = (const float*)d_in[20];
    float* out = (float*)d_out;

    float *QN, *HID;
    cudaGetSymbolAddress((void**)&QN, g_QN);
    cudaGetSymbolAddress((void**)&HID, g_HID);

    init_kernel<<<1, 128>>>();
    ln3_kernel<<<dim3(NROWS/8, 3), 256>>>(queries, keys, values,
                                          ln_q_g, ln_q_b, ln_k_g, ln_k_b, ln_v_g, ln_v_b);
    wconv4_kernel<<<dim3(DD*DD/4/256, 4), 256>>>(Wq, Wk, Wv, Wo);

    // window MLP hidden (fp32 — rintf-sensitive path)
    gemm_kernel<<<dim3(2, 64), 256>>>(QN, Ww1, bw1, HID, 128, 1);
    winred_kernel<<<NROWS, 128>>>(Ww2, bw2);

    dm_kernel<<<NROWS, 256>>>();
    batchstat_kernel<<<BB, 1024>>>();
    kp_kernel<<<BB, 1024>>>();
    gumbel_kernel<<<BB * 4, 512>>>();
    maskbuild_kernel<<<NROWS, 64>>>();
    needed_kernel<<<1, 32>>>();
    fill_kernel<<<2048, 256>>>();

    // fused Q/K/V projections (fp16 MMA; Q pre-scaled 1/8)
    qkv_h_kernel<<<dim3(8, 64, 3), 128>>>(bq, bk, bv);

    // V transpose for PV B-fragments
    vtrans_kernel<<<dim3(NROWS/32, DD/32), 256>>>();

    // attention (fp16 MMA flash, cp.async double buffer)
    attn_h2_kernel<<<dim3(SS / 128, BB * HH), 256>>>();

    // output projection + residual (fp16 MMA, fp32 out)
    oproj_h_kernel<<<dim3(8, 64), 128>>>(bo, queries, out);
}